// round 7
// baseline (speedup 1.0000x reference)
#include <cuda_runtime.h>
#include <cuda_bf16.h>
#include <cstdint>

// Problem constants
#define B_SZ 4
#define N_SEQ 2048
#define D_MODEL 1024
#define N_HEADS 16
#define HEAD_DIM 64
#define BH (B_SZ * N_HEADS)          // 64
#define TOKENS (B_SZ * N_SEQ)        // 8192
#define QKV_COLS (3 * D_MODEL)       // 3072

// Scratch (module-static device memory; no runtime allocation)
__device__ float g_qkv[3ull * BH * N_SEQ * HEAD_DIM];   // [sel][bh][n][dh]
__device__ float g_att[(size_t)TOKENS * D_MODEL];       // [b][n][h][dh]

// ---------------------------------------------------------------------------
// Helpers
// ---------------------------------------------------------------------------
__device__ __forceinline__ uint32_t smem_u32(const void* p) {
    uint32_t a;
    asm("{ .reg .u64 t; cvta.to.shared.u64 t, %1; cvt.u32.u64 %0, t; }"
        : "=r"(a) : "l"(p));
    return a;
}

__device__ __forceinline__ void split_bf16(float x, unsigned short& h, unsigned short& l) {
    __nv_bfloat16 bh = __float2bfloat16(x);
    float r = x - __bfloat162float(bh);
    __nv_bfloat16 bl = __float2bfloat16(r);
    h = __bfloat16_as_ushort(bh);
    l = __bfloat16_as_ushort(bl);
}

#define LDSM_X4(r0, r1, r2, r3, addr) \
    asm volatile("ldmatrix.sync.aligned.m8n8.x4.shared.b16 {%0,%1,%2,%3}, [%4];" \
                 : "=r"(r0), "=r"(r1), "=r"(r2), "=r"(r3) : "r"(addr))

#define MMA_BF16(c, a, b0, b1) \
    asm volatile("mma.sync.aligned.m16n8k16.row.col.f32.bf16.bf16.f32 " \
                 "{%0,%1,%2,%3}, {%4,%5,%6,%7}, {%8,%9}, {%0,%1,%2,%3};" \
                 : "+f"((c)[0]), "+f"((c)[1]), "+f"((c)[2]), "+f"((c)[3]) \
                 : "r"((a)[0]), "r"((a)[1]), "r"((a)[2]), "r"((a)[3]), \
                   "r"(b0), "r"(b1))

// ---------------------------------------------------------------------------
// Warp-MMA split-bf16 GEMM: C[M,N] = A[M,K] @ B[K,N] + bias[N]
// A, B fp32 row-major. BM=BN=128, BK=32, 256 threads (8 warps, 4x2 grid),
// warp tile 32x64 via m16n8k16. Split: D = Ah*Bh + Ah*Bl + Al*Bh (fp32 acc).
// mode 0: scatter into g_qkv ([sel][bh][n][dh]); mode 1: plain write into C.
// ---------------------------------------------------------------------------
#define SSTRIDE 40   // bf16 elems per smem row (32 + 8 pad) -> 80B, LDSM conflict-free

__global__ void __launch_bounds__(256)
mma_gemm_kernel(const float* __restrict__ A, const float* __restrict__ Bm,
                const float* __restrict__ bias, float* __restrict__ C,
                int M, int N, int K, int mode)
{
    __shared__ __nv_bfloat16 Ah[128 * SSTRIDE];
    __shared__ __nv_bfloat16 Al[128 * SSTRIDE];
    __shared__ __nv_bfloat16 Bh[128 * SSTRIDE];
    __shared__ __nv_bfloat16 Bl[128 * SSTRIDE];

    const int tid  = threadIdx.x;
    const int wid  = tid >> 5;
    const int lane = tid & 31;
    const int wr   = wid >> 1;      // 0..3 -> rows wr*32..+31
    const int wc   = wid & 1;       // 0..1 -> cols wc*64..+63

    const int row0 = blockIdx.y * 128;
    const int col0 = blockIdx.x * 128;

    const uint32_t ah_b = smem_u32(Ah);
    const uint32_t al_b = smem_u32(Al);
    const uint32_t bh_b = smem_u32(Bh);
    const uint32_t bl_b = smem_u32(Bl);

    float acc[2][8][4];
#pragma unroll
    for (int i = 0; i < 2; i++)
#pragma unroll
        for (int j = 0; j < 8; j++)
#pragma unroll
            for (int c = 0; c < 4; c++) acc[i][j][c] = 0.f;

    // ldmatrix lane addressing (precomputed element offsets within tile)
    const uint32_t a_row = lane & 15;                 // m within 16
    const uint32_t a_kof = (lane >> 4) << 3;          // 0 or 8
    const uint32_t b_nof = ((lane >> 4) << 3) + (lane & 7);   // n within 16
    const uint32_t b_kof = ((lane >> 3) & 1) << 3;    // 0 or 8

    for (int k0 = 0; k0 < K; k0 += 32) {
        // ---- Load + split A chunk [128 x 32] (K-major)
#pragma unroll
        for (int i = 0; i < 4; i++) {
            int f  = i * 256 + tid;         // 0..1023 float4s
            int r  = f >> 3;                // 0..127
            int c4 = (f & 7) << 2;          // 0..28
            float4 v = *(const float4*)(A + (size_t)(row0 + r) * K + k0 + c4);
            float xv[4] = {v.x, v.y, v.z, v.w};
            unsigned short sh[4], sl[4];
#pragma unroll
            for (int j = 0; j < 4; j++) split_bf16(xv[j], sh[j], sl[j]);
            uint32_t off = ((uint32_t)r * SSTRIDE + c4) * 2;   // bytes, 8B aligned
            uint2 uh, ul;
            uh.x = (uint32_t)sh[0] | ((uint32_t)sh[1] << 16);
            uh.y = (uint32_t)sh[2] | ((uint32_t)sh[3] << 16);
            ul.x = (uint32_t)sl[0] | ((uint32_t)sl[1] << 16);
            ul.y = (uint32_t)sl[2] | ((uint32_t)sl[3] << 16);
            *(uint2*)((char*)Ah + off) = uh;
            *(uint2*)((char*)Al + off) = ul;
        }
        // ---- Load + split + transpose B chunk: Bs[n][k], n:128, k:32
#pragma unroll
        for (int i = 0; i < 4; i++) {
            int f  = i * 256 + tid;
            int kk = f >> 5;                // 0..31
            int n4 = (f & 31) << 2;         // 0..124
            float4 v = *(const float4*)(Bm + (size_t)(k0 + kk) * N + col0 + n4);
            float xv[4] = {v.x, v.y, v.z, v.w};
#pragma unroll
            for (int j = 0; j < 4; j++) {
                unsigned short h, l;
                split_bf16(xv[j], h, l);
                uint32_t off = (uint32_t)(n4 + j) * SSTRIDE + kk;
                Bh[off] = __ushort_as_bfloat16(h);
                Bl[off] = __ushort_as_bfloat16(l);
            }
        }
        __syncthreads();

        // ---- MMA over 2 k16 steps
#pragma unroll
        for (int ks = 0; ks < 2; ks++) {
            const uint32_t kk = ks * 16;
            uint32_t ahr[2][4], alr[2][4];
#pragma unroll
            for (int i = 0; i < 2; i++) {
                uint32_t eoff = ((wr * 32 + i * 16 + a_row) * SSTRIDE + kk + a_kof) * 2;
                LDSM_X4(ahr[i][0], ahr[i][1], ahr[i][2], ahr[i][3], ah_b + eoff);
                LDSM_X4(alr[i][0], alr[i][1], alr[i][2], alr[i][3], al_b + eoff);
            }
#pragma unroll
            for (int jp = 0; jp < 4; jp++) {
                const uint32_t nb = wc * 64 + jp * 16;
                uint32_t eoff = ((nb + b_nof) * SSTRIDE + kk + b_kof) * 2;
                uint32_t bhr[4], blr[4];
                LDSM_X4(bhr[0], bhr[1], bhr[2], bhr[3], bh_b + eoff);
                LDSM_X4(blr[0], blr[1], blr[2], blr[3], bl_b + eoff);
#pragma unroll
                for (int i = 0; i < 2; i++) {
                    MMA_BF16(acc[i][2 * jp + 0], ahr[i], bhr[0], bhr[1]);
                    MMA_BF16(acc[i][2 * jp + 1], ahr[i], bhr[2], bhr[3]);
                    MMA_BF16(acc[i][2 * jp + 0], ahr[i], blr[0], blr[1]);
                    MMA_BF16(acc[i][2 * jp + 1], ahr[i], blr[2], blr[3]);
                    MMA_BF16(acc[i][2 * jp + 0], alr[i], bhr[0], bhr[1]);
                    MMA_BF16(acc[i][2 * jp + 1], alr[i], bhr[2], bhr[3]);
                }
            }
        }
        __syncthreads();
    }

    // ---- Epilogue. acc[i][j]: c0,c1 -> m = base + lane/4, n = nb + 2*(lane%4)+{0,1};
    //                           c2,c3 -> m + 8, same n.
    const int mbase = row0 + wr * 32 + (lane >> 2);
    const int nbase = col0 + wc * 64 + ((lane & 3) << 1);

    if (mode == 0) {
#pragma unroll
        for (int i = 0; i < 2; i++) {
#pragma unroll
            for (int rr = 0; rr < 2; rr++) {
                const int m  = mbase + i * 16 + rr * 8;
                const int bb = m >> 11;
                const int nn = m & 2047;
#pragma unroll
                for (int j = 0; j < 8; j++) {
#pragma unroll
                    for (int c = 0; c < 2; c++) {
                        const int jg  = nbase + j * 8 + c;
                        const int sel = jg >> 10;
                        const int hh  = (jg >> 6) & 15;
                        const int dh  = jg & 63;
                        g_qkv[((size_t)(sel * BH + (bb * N_HEADS + hh)) * N_SEQ + nn) * HEAD_DIM + dh] =
                            acc[i][j][rr * 2 + c] + bias[jg];
                    }
                }
            }
        }
    } else {
#pragma unroll
        for (int i = 0; i < 2; i++) {
#pragma unroll
            for (int rr = 0; rr < 2; rr++) {
                const int m = mbase + i * 16 + rr * 8;
                float* cp = C + (size_t)m * N;
#pragma unroll
                for (int j = 0; j < 8; j++) {
#pragma unroll
                    for (int c = 0; c < 2; c++) {
                        const int jg = nbase + j * 8 + c;
                        cp[jg] = acc[i][j][rr * 2 + c] + bias[jg];
                    }
                }
            }
        }
    }
}

// ---------------------------------------------------------------------------
// Flash attention (fp32): one CTA per (bh, 64-query tile). Br=Bc=64, d=64.
// ---------------------------------------------------------------------------
#define APITCH 68
#define AT_SMEM_FLOATS (4 * 64 * APITCH)
#define AT_SMEM_BYTES (AT_SMEM_FLOATS * 4)

__global__ void __launch_bounds__(256, 2)
attn_kernel()
{
    extern __shared__ float sm[];
    float (*Qt)[APITCH] = (float(*)[APITCH])(sm);
    float (*Kt)[APITCH] = (float(*)[APITCH])(sm + 64 * APITCH);
    float (*Vs)[APITCH] = (float(*)[APITCH])(sm + 2 * 64 * APITCH);
    float (*Ps)[APITCH] = (float(*)[APITCH])(sm + 3 * 64 * APITCH);

    const int tid = threadIdx.x;
    const int ty = tid >> 4;
    const int tx = tid & 15;
    const int bh = blockIdx.y;
    const int qt = blockIdx.x;

    const float* Qg  = g_qkv + ((size_t)(0 * BH + bh) * N_SEQ + qt * 64) * HEAD_DIM;
    const float* Kg0 = g_qkv + (size_t)(1 * BH + bh) * N_SEQ * HEAD_DIM;
    const float* Vg0 = g_qkv + (size_t)(2 * BH + bh) * N_SEQ * HEAD_DIM;

    const float SCALE = 0.125f;

#pragma unroll
    for (int it = 0; it < 4; it++) {
        int f = it * 256 + tid;
        int r = f >> 4;
        int c4 = (f & 15) << 2;
        float4 v = *(const float4*)(Qg + r * HEAD_DIM + c4);
        Qt[c4 + 0][r] = v.x * SCALE;
        Qt[c4 + 1][r] = v.y * SCALE;
        Qt[c4 + 2][r] = v.z * SCALE;
        Qt[c4 + 3][r] = v.w * SCALE;
    }

    float m_r[4], l_r[4], o[4][4];
#pragma unroll
    for (int i = 0; i < 4; i++) {
        m_r[i] = -1e30f;
        l_r[i] = 0.f;
#pragma unroll
        for (int j = 0; j < 4; j++) o[i][j] = 0.f;
    }

    for (int kt = 0; kt < N_SEQ / 64; kt++) {
        const float* Kg = Kg0 + (size_t)kt * 64 * HEAD_DIM;
        const float* Vg = Vg0 + (size_t)kt * 64 * HEAD_DIM;
#pragma unroll
        for (int it = 0; it < 4; it++) {
            int f = it * 256 + tid;
            int r = f >> 4;
            int c4 = (f & 15) << 2;
            float4 kv = *(const float4*)(Kg + r * HEAD_DIM + c4);
            Kt[c4 + 0][r] = kv.x;
            Kt[c4 + 1][r] = kv.y;
            Kt[c4 + 2][r] = kv.z;
            Kt[c4 + 3][r] = kv.w;
            *(float4*)&Vs[r][c4] = *(const float4*)(Vg + r * HEAD_DIM + c4);
        }
        __syncthreads();

        float s[4][4];
#pragma unroll
        for (int i = 0; i < 4; i++)
#pragma unroll
            for (int j = 0; j < 4; j++) s[i][j] = 0.f;

#pragma unroll 8
        for (int k = 0; k < 64; k++) {
            float4 a = *(float4*)&Qt[k][ty * 4];
            float4 b = *(float4*)&Kt[k][tx * 4];
            float ar[4] = {a.x, a.y, a.z, a.w};
            float br[4] = {b.x, b.y, b.z, b.w};
#pragma unroll
            for (int i = 0; i < 4; i++)
#pragma unroll
                for (int j = 0; j < 4; j++)
                    s[i][j] += ar[i] * br[j];
        }

#pragma unroll
        for (int i = 0; i < 4; i++) {
            float mloc = fmaxf(fmaxf(s[i][0], s[i][1]), fmaxf(s[i][2], s[i][3]));
#pragma unroll
            for (int w = 1; w < 16; w <<= 1)
                mloc = fmaxf(mloc, __shfl_xor_sync(0xffffffffu, mloc, w));
            float mnew = fmaxf(m_r[i], mloc);
            float sc = __expf(m_r[i] - mnew);
            float lsum = 0.f;
#pragma unroll
            for (int j = 0; j < 4; j++) {
                float p = __expf(s[i][j] - mnew);
                s[i][j] = p;
                lsum += p;
            }
#pragma unroll
            for (int w = 1; w < 16; w <<= 1)
                lsum += __shfl_xor_sync(0xffffffffu, lsum, w);
            l_r[i] = l_r[i] * sc + lsum;
            m_r[i] = mnew;
#pragma unroll
            for (int j = 0; j < 4; j++) o[i][j] *= sc;
            *(float4*)&Ps[ty * 4 + i][tx * 4] = make_float4(s[i][0], s[i][1], s[i][2], s[i][3]);
        }
        __syncthreads();

#pragma unroll 8
        for (int c = 0; c < 64; c++) {
            float4 v = *(float4*)&Vs[c][tx * 4];
            float vr[4] = {v.x, v.y, v.z, v.w};
#pragma unroll
            for (int i = 0; i < 4; i++) {
                float p = Ps[ty * 4 + i][c];
#pragma unroll
                for (int j = 0; j < 4; j++)
                    o[i][j] += p * vr[j];
            }
        }
        __syncthreads();
    }

    const int b = bh >> 4;
    const int h = bh & 15;
#pragma unroll
    for (int i = 0; i < 4; i++) {
        float inv_l = 1.0f / l_r[i];
        int qrow = qt * 64 + ty * 4 + i;
        float4 v = make_float4(o[i][0] * inv_l, o[i][1] * inv_l,
                               o[i][2] * inv_l, o[i][3] * inv_l);
        *(float4*)(g_att + ((size_t)(b * N_SEQ + qrow) * N_HEADS + h) * HEAD_DIM + tx * 4) = v;
    }
}

// ---------------------------------------------------------------------------
// Launch
// ---------------------------------------------------------------------------
extern "C" void kernel_launch(void* const* d_in, const int* in_sizes, int n_in,
                              void* d_out, int out_size)
{
    const float* x      = (const float*)d_in[0];
    const float* W_qkv  = (const float*)d_in[1];
    const float* b_qkv  = (const float*)d_in[2];
    const float* W_out  = (const float*)d_in[3];
    const float* b_out  = (const float*)d_in[4];
    float* out = (float*)d_out;

    float* g_att_ptr = nullptr;
    cudaGetSymbolAddress((void**)&g_att_ptr, g_att);

    static bool attr_set = false;
    if (!attr_set) {
        cudaFuncSetAttribute(attn_kernel,
                             cudaFuncAttributeMaxDynamicSharedMemorySize,
                             AT_SMEM_BYTES);
        attr_set = true;
    }

    // 1) QKV projection (warp-MMA split-bf16) with scatter epilogue
    {
        dim3 grid(QKV_COLS / 128, TOKENS / 128);
        mma_gemm_kernel<<<grid, 256>>>(x, W_qkv, b_qkv, nullptr,
                                       TOKENS, QKV_COLS, D_MODEL, 0);
    }

    // 2) Flash attention (fp32)
    {
        dim3 grid(N_SEQ / 64, BH);
        attn_kernel<<<grid, 256, AT_SMEM_BYTES>>>();
    }

    // 3) Output projection (warp-MMA split-bf16)
    {
        dim3 grid(D_MODEL / 128, TOKENS / 128);
        mma_gemm_kernel<<<grid, 256>>>(g_att_ptr, W_out, b_out, out,
                                       TOKENS, D_MODEL, D_MODEL, 1);
    }
}

// round 8
// speedup vs baseline: 2.3461x; 2.3461x over previous
#include <cuda_runtime.h>
#include <cuda_bf16.h>
#include <cstdint>

// Problem constants
#define B_SZ 4
#define N_SEQ 2048
#define D_MODEL 1024
#define N_HEADS 16
#define HEAD_DIM 64
#define BH (B_SZ * N_HEADS)          // 64
#define TOKENS (B_SZ * N_SEQ)        // 8192
#define QKV_COLS (3 * D_MODEL)       // 3072

typedef __nv_bfloat16 bf16;

// ---------------------------------------------------------------------------
// Scratch (module-static device memory; no runtime allocation)
// ---------------------------------------------------------------------------
#define QKV_ELEMS ((size_t)BH * N_SEQ * HEAD_DIM)   // 8388608
__device__ bf16 g_x_hi[(size_t)TOKENS * D_MODEL];
__device__ bf16 g_x_lo[(size_t)TOKENS * D_MODEL];
__device__ bf16 g_wqkv_hi[(size_t)QKV_COLS * D_MODEL];   // [n][k]
__device__ bf16 g_wqkv_lo[(size_t)QKV_COLS * D_MODEL];
__device__ bf16 g_wout_hi[(size_t)D_MODEL * D_MODEL];    // [n][k]
__device__ bf16 g_wout_lo[(size_t)D_MODEL * D_MODEL];
__device__ bf16 g_q_hi[QKV_ELEMS];   // [bh][n][dh], pre-scaled by 0.125
__device__ bf16 g_q_lo[QKV_ELEMS];
__device__ bf16 g_k_hi[QKV_ELEMS];   // [bh][n][dh]
__device__ bf16 g_k_lo[QKV_ELEMS];
__device__ bf16 g_vt_hi[QKV_ELEMS];  // [bh][dh][n]  (transposed)
__device__ bf16 g_vt_lo[QKV_ELEMS];
__device__ bf16 g_att_hi[(size_t)TOKENS * D_MODEL];  // [token][h*64+dh]
__device__ bf16 g_att_lo[(size_t)TOKENS * D_MODEL];

// ---------------------------------------------------------------------------
// Helpers
// ---------------------------------------------------------------------------
__device__ __forceinline__ uint32_t smem_u32(const void* p) {
    uint32_t a;
    asm("{ .reg .u64 t; cvta.to.shared.u64 t, %1; cvt.u32.u64 %0, t; }"
        : "=r"(a) : "l"(p));
    return a;
}

__device__ __forceinline__ void split1(float x, unsigned short& h, unsigned short& l) {
    bf16 bh_ = __float2bfloat16(x);
    float r = x - __bfloat162float(bh_);
    bf16 bl_ = __float2bfloat16(r);
    h = __bfloat16_as_ushort(bh_);
    l = __bfloat16_as_ushort(bl_);
}

// pack pair (x -> low 16 bits, y -> high 16 bits)
__device__ __forceinline__ void split_pack2(float x, float y, uint32_t& hi, uint32_t& lo) {
    unsigned short hx, lx, hy, ly;
    split1(x, hx, lx);
    split1(y, hy, ly);
    hi = (uint32_t)hx | ((uint32_t)hy << 16);
    lo = (uint32_t)lx | ((uint32_t)ly << 16);
}

#define LDSM_X4(r0, r1, r2, r3, addr) \
    asm volatile("ldmatrix.sync.aligned.m8n8.x4.shared.b16 {%0,%1,%2,%3}, [%4];" \
                 : "=r"(r0), "=r"(r1), "=r"(r2), "=r"(r3) : "r"(addr))

#define MMA_BF16(c, a, b0, b1) \
    asm volatile("mma.sync.aligned.m16n8k16.row.col.f32.bf16.bf16.f32 " \
                 "{%0,%1,%2,%3}, {%4,%5,%6,%7}, {%8,%9}, {%0,%1,%2,%3};" \
                 : "+f"((c)[0]), "+f"((c)[1]), "+f"((c)[2]), "+f"((c)[3]) \
                 : "r"((a)[0]), "r"((a)[1]), "r"((a)[2]), "r"((a)[3]), \
                   "r"(b0), "r"(b1))

// ---------------------------------------------------------------------------
// Conversion kernels
// ---------------------------------------------------------------------------
__global__ void split_x_kernel(const float* __restrict__ x, bf16* __restrict__ hi,
                               bf16* __restrict__ lo, int n4)
{
    int idx = blockIdx.x * 256 + threadIdx.x;
    if (idx >= n4) return;
    float4 v = ((const float4*)x)[idx];
    uint32_t h0, l0, h1, l1;
    split_pack2(v.x, v.y, h0, l0);
    split_pack2(v.z, v.w, h1, l1);
    ((uint2*)hi)[idx] = make_uint2(h0, h1);
    ((uint2*)lo)[idx] = make_uint2(l0, l1);
}

// W[k][n] fp32 -> Wt[n][k] split bf16 (tiled transpose)
__global__ void split_wt_kernel(const float* __restrict__ W, bf16* __restrict__ hi,
                                bf16* __restrict__ lo, int N, int K)
{
    __shared__ float t[32][33];
    const int tx = threadIdx.x, ty = threadIdx.y;  // block (32,8)
    const int n0 = blockIdx.x * 32, k0 = blockIdx.y * 32;
#pragma unroll
    for (int s = 0; s < 4; s++)
        t[ty + 8 * s][tx] = W[(size_t)(k0 + ty + 8 * s) * N + n0 + tx];
    __syncthreads();
#pragma unroll
    for (int s = 0; s < 4; s++) {
        const int nn = ty + 8 * s, kk = tx;
        float v = t[kk][nn];
        unsigned short h, l;
        split1(v, h, l);
        hi[(size_t)(n0 + nn) * K + k0 + kk] = __ushort_as_bfloat16(h);
        lo[(size_t)(n0 + nn) * K + k0 + kk] = __ushort_as_bfloat16(l);
    }
}

// ---------------------------------------------------------------------------
// Warp-MMA split-bf16 GEMM (pre-split inputs):
// C[M,N] = A[M,K] @ Bt[N,K]^T + bias[N].  BM=BN=128, BK=32, 256 thr, 8 warps.
// mode 0: scatter into q/k/vt split arrays (QKV); mode 1: fp32 write + bias.
// ---------------------------------------------------------------------------
#define SSTRIDE 40

__global__ void __launch_bounds__(256)
mma_gemm_kernel(const bf16* __restrict__ Ah_g, const bf16* __restrict__ Al_g,
                const bf16* __restrict__ Bh_g, const bf16* __restrict__ Bl_g,
                const float* __restrict__ bias, float* __restrict__ C,
                int M, int N, int K, int mode)
{
    __shared__ __align__(16) bf16 Ah[128 * SSTRIDE];
    __shared__ __align__(16) bf16 Al[128 * SSTRIDE];
    __shared__ __align__(16) bf16 Bh[128 * SSTRIDE];
    __shared__ __align__(16) bf16 Bl[128 * SSTRIDE];

    const int tid  = threadIdx.x;
    const int wid  = tid >> 5;
    const int lane = tid & 31;
    const int wr   = wid >> 1;
    const int wc   = wid & 1;

    const int row0 = blockIdx.y * 128;
    const int col0 = blockIdx.x * 128;

    const uint32_t ah_b = smem_u32(Ah);
    const uint32_t al_b = smem_u32(Al);
    const uint32_t bh_b = smem_u32(Bh);
    const uint32_t bl_b = smem_u32(Bl);

    float acc[2][8][4];
#pragma unroll
    for (int i = 0; i < 2; i++)
#pragma unroll
        for (int j = 0; j < 8; j++)
#pragma unroll
            for (int c = 0; c < 4; c++) acc[i][j][c] = 0.f;

    const uint32_t a_row = lane & 15;
    const uint32_t a_kof = (lane >> 4) << 3;
    const uint32_t b_nof = ((lane >> 4) << 3) + (lane & 7);
    const uint32_t b_kof = ((lane >> 3) & 1) << 3;

    for (int k0 = 0; k0 < K; k0 += 32) {
        // Loads: per array 512 uint4 (128 rows x 4 uint4 of 8 bf16)
#pragma unroll
        for (int i = 0; i < 2; i++) {
            int f  = i * 256 + tid;
            int r  = f >> 2;
            int c8 = (f & 3) << 3;
            size_t ga = (size_t)(row0 + r) * K + k0 + c8;
            size_t gb = (size_t)(col0 + r) * K + k0 + c8;
            uint32_t so = ((uint32_t)r * SSTRIDE + c8) * 2;
            *(uint4*)((char*)Ah + so) = *(const uint4*)(Ah_g + ga);
            *(uint4*)((char*)Al + so) = *(const uint4*)(Al_g + ga);
            *(uint4*)((char*)Bh + so) = *(const uint4*)(Bh_g + gb);
            *(uint4*)((char*)Bl + so) = *(const uint4*)(Bl_g + gb);
        }
        __syncthreads();

#pragma unroll
        for (int ks = 0; ks < 2; ks++) {
            const uint32_t kk = ks * 16;
            uint32_t ahr[2][4], alr[2][4];
#pragma unroll
            for (int i = 0; i < 2; i++) {
                uint32_t eoff = ((wr * 32 + i * 16 + a_row) * SSTRIDE + kk + a_kof) * 2;
                LDSM_X4(ahr[i][0], ahr[i][1], ahr[i][2], ahr[i][3], ah_b + eoff);
                LDSM_X4(alr[i][0], alr[i][1], alr[i][2], alr[i][3], al_b + eoff);
            }
#pragma unroll
            for (int jp = 0; jp < 4; jp++) {
                const uint32_t nb = wc * 64 + jp * 16;
                uint32_t eoff = ((nb + b_nof) * SSTRIDE + kk + b_kof) * 2;
                uint32_t bhr[4], blr[4];
                LDSM_X4(bhr[0], bhr[1], bhr[2], bhr[3], bh_b + eoff);
                LDSM_X4(blr[0], blr[1], blr[2], blr[3], bl_b + eoff);
#pragma unroll
                for (int i = 0; i < 2; i++) {
                    MMA_BF16(acc[i][2 * jp + 0], ahr[i], bhr[0], bhr[1]);
                    MMA_BF16(acc[i][2 * jp + 1], ahr[i], bhr[2], bhr[3]);
                    MMA_BF16(acc[i][2 * jp + 0], ahr[i], blr[0], blr[1]);
                    MMA_BF16(acc[i][2 * jp + 1], ahr[i], blr[2], blr[3]);
                    MMA_BF16(acc[i][2 * jp + 0], alr[i], bhr[0], bhr[1]);
                    MMA_BF16(acc[i][2 * jp + 1], alr[i], bhr[2], bhr[3]);
                }
            }
        }
        __syncthreads();
    }

    const int mbase = row0 + wr * 32 + (lane >> 2);
    const int nbase = col0 + wc * 64 + ((lane & 3) << 1);

    if (mode == 0) {
#pragma unroll
        for (int i = 0; i < 2; i++) {
#pragma unroll
            for (int rr = 0; rr < 2; rr++) {
                const int m  = mbase + i * 16 + rr * 8;
                const int bb = m >> 11;
                const int nn = m & 2047;
#pragma unroll
                for (int j = 0; j < 8; j++) {
                    const int jg0 = nbase + j * 8;     // even
                    const int sel = jg0 >> 10;
                    const int hh  = (jg0 >> 6) & 15;
                    const int dh  = jg0 & 63;
                    const int bhd = bb * N_HEADS + hh;
                    float v0 = acc[i][j][rr * 2 + 0] + bias[jg0];
                    float v1 = acc[i][j][rr * 2 + 1] + bias[jg0 + 1];
                    if (sel == 0) { v0 *= 0.125f; v1 *= 0.125f; }
                    uint32_t ph, pl;
                    split_pack2(v0, v1, ph, pl);
                    if (sel == 0) {
                        size_t o = ((size_t)bhd * N_SEQ + nn) * HEAD_DIM + dh;
                        *(uint32_t*)&g_q_hi[o] = ph;
                        *(uint32_t*)&g_q_lo[o] = pl;
                    } else if (sel == 1) {
                        size_t o = ((size_t)bhd * N_SEQ + nn) * HEAD_DIM + dh;
                        *(uint32_t*)&g_k_hi[o] = ph;
                        *(uint32_t*)&g_k_lo[o] = pl;
                    } else {
                        size_t o = ((size_t)bhd * HEAD_DIM + dh) * N_SEQ + nn;
                        g_vt_hi[o] = __ushort_as_bfloat16((unsigned short)(ph & 0xffff));
                        g_vt_lo[o] = __ushort_as_bfloat16((unsigned short)(pl & 0xffff));
                        g_vt_hi[o + N_SEQ] = __ushort_as_bfloat16((unsigned short)(ph >> 16));
                        g_vt_lo[o + N_SEQ] = __ushort_as_bfloat16((unsigned short)(pl >> 16));
                    }
                }
            }
        }
    } else {
#pragma unroll
        for (int i = 0; i < 2; i++) {
#pragma unroll
            for (int rr = 0; rr < 2; rr++) {
                const int m = mbase + i * 16 + rr * 8;
                float* cp = C + (size_t)m * N;
#pragma unroll
                for (int j = 0; j < 8; j++) {
#pragma unroll
                    for (int c = 0; c < 2; c++) {
                        const int jg = nbase + j * 8 + c;
                        cp[jg] = acc[i][j][rr * 2 + c] + bias[jg];
                    }
                }
            }
        }
    }
}

// ---------------------------------------------------------------------------
// mma.sync flash attention. CTA: (head bh, 128-query tile). 8 warps x m16.
// S = Q@K^T (3-term split), online softmax, PV (3-term split), all fp32 accum.
// smem: Qh/Ql [128][72], Kh/Kl [64][72], Vh/Vl [64][72]  = 73728 B dynamic.
// ---------------------------------------------------------------------------
#define AQ_STR 72
#define ATT_SMEM_BYTES ((128 + 128 + 64 + 64 + 64 + 64) * AQ_STR * 2)

__global__ void __launch_bounds__(256)
attn_mma_kernel()
{
    extern __shared__ __align__(16) bf16 smb[];
    bf16* Qh = smb;
    bf16* Ql = Qh + 128 * AQ_STR;
    bf16* Kh = Ql + 128 * AQ_STR;
    bf16* Kl = Kh + 64 * AQ_STR;
    bf16* Vh = Kl + 64 * AQ_STR;
    bf16* Vl = Vh + 64 * AQ_STR;

    const int tid  = threadIdx.x;
    const int w    = tid >> 5;
    const int lane = tid & 31;
    const int bh   = blockIdx.y;
    const int qt   = blockIdx.x;

    const uint32_t qh_b = smem_u32(Qh);
    const uint32_t ql_b = smem_u32(Ql);
    const uint32_t kh_b = smem_u32(Kh);
    const uint32_t kl_b = smem_u32(Kl);
    const uint32_t vh_b = smem_u32(Vh);
    const uint32_t vl_b = smem_u32(Vl);

    // Load Q tile [128][64] hi/lo
    const bf16* qsrc_h = g_q_hi + ((size_t)bh * N_SEQ + qt * 128) * HEAD_DIM;
    const bf16* qsrc_l = g_q_lo + ((size_t)bh * N_SEQ + qt * 128) * HEAD_DIM;
#pragma unroll
    for (int i = 0; i < 4; i++) {
        int f  = i * 256 + tid;       // 1024 uint4 per array
        int r  = f >> 3;
        int c8 = (f & 7) << 3;
        uint32_t so = ((uint32_t)r * AQ_STR + c8) * 2;
        *(uint4*)((char*)Qh + so) = *(const uint4*)(qsrc_h + r * HEAD_DIM + c8);
        *(uint4*)((char*)Ql + so) = *(const uint4*)(qsrc_l + r * HEAD_DIM + c8);
    }
    __syncthreads();

    const uint32_t a_row = lane & 15;
    const uint32_t a_kof = (lane >> 4) << 3;
    const uint32_t b_nof = ((lane >> 4) << 3) + (lane & 7);
    const uint32_t b_kof = ((lane >> 3) & 1) << 3;

    // Q fragments in registers (4 k-steps)
    uint32_t qfh[4][4], qfl[4][4];
#pragma unroll
    for (int t = 0; t < 4; t++) {
        uint32_t eoff = ((w * 16 + a_row) * AQ_STR + t * 16 + a_kof) * 2;
        LDSM_X4(qfh[t][0], qfh[t][1], qfh[t][2], qfh[t][3], qh_b + eoff);
        LDSM_X4(qfl[t][0], qfl[t][1], qfl[t][2], qfl[t][3], ql_b + eoff);
    }

    float m0 = -1e30f, m1 = -1e30f, l0 = 0.f, l1 = 0.f;
    float o[8][4];
#pragma unroll
    for (int j = 0; j < 8; j++)
#pragma unroll
        for (int c = 0; c < 4; c++) o[j][c] = 0.f;

    const bf16* ksrc_h = g_k_hi + (size_t)bh * N_SEQ * HEAD_DIM;
    const bf16* ksrc_l = g_k_lo + (size_t)bh * N_SEQ * HEAD_DIM;
    const bf16* vsrc_h = g_vt_hi + (size_t)bh * HEAD_DIM * N_SEQ;
    const bf16* vsrc_l = g_vt_lo + (size_t)bh * HEAD_DIM * N_SEQ;

    for (int kt = 0; kt < N_SEQ / 64; kt++) {
        // Load K [64 n][64 k] and Vt [64 d][64 kseq] hi/lo
#pragma unroll
        for (int i = 0; i < 2; i++) {
            int f  = i * 256 + tid;     // 512 uint4 per array
            int r  = f >> 3;
            int c8 = (f & 7) << 3;
            uint32_t so = ((uint32_t)r * AQ_STR + c8) * 2;
            size_t gk = (size_t)(kt * 64 + r) * HEAD_DIM + c8;
            size_t gv = (size_t)r * N_SEQ + kt * 64 + c8;
            *(uint4*)((char*)Kh + so) = *(const uint4*)(ksrc_h + gk);
            *(uint4*)((char*)Kl + so) = *(const uint4*)(ksrc_l + gk);
            *(uint4*)((char*)Vh + so) = *(const uint4*)(vsrc_h + gv);
            *(uint4*)((char*)Vl + so) = *(const uint4*)(vsrc_l + gv);
        }
        __syncthreads();

        // S = Q @ K^T (scale pre-folded into Q)
        float s[8][4];
#pragma unroll
        for (int j = 0; j < 8; j++)
#pragma unroll
            for (int c = 0; c < 4; c++) s[j][c] = 0.f;

#pragma unroll
        for (int t = 0; t < 4; t++) {
#pragma unroll
            for (int g = 0; g < 4; g++) {
                uint32_t eoff = ((g * 16 + b_nof) * AQ_STR + t * 16 + b_kof) * 2;
                uint32_t kh4[4], kl4[4];
                LDSM_X4(kh4[0], kh4[1], kh4[2], kh4[3], kh_b + eoff);
                LDSM_X4(kl4[0], kl4[1], kl4[2], kl4[3], kl_b + eoff);
                MMA_BF16(s[2 * g + 0], qfh[t], kh4[0], kh4[1]);
                MMA_BF16(s[2 * g + 1], qfh[t], kh4[2], kh4[3]);
                MMA_BF16(s[2 * g + 0], qfh[t], kl4[0], kl4[1]);
                MMA_BF16(s[2 * g + 1], qfh[t], kl4[2], kl4[3]);
                MMA_BF16(s[2 * g + 0], qfl[t], kh4[0], kh4[1]);
                MMA_BF16(s[2 * g + 1], qfl[t], kh4[2], kh4[3]);
            }
        }

        // Online softmax. Row half 0 -> s[j][0..1], half 1 -> s[j][2..3]
        float mx0 = -1e30f, mx1 = -1e30f;
#pragma unroll
        for (int j = 0; j < 8; j++) {
            mx0 = fmaxf(mx0, fmaxf(s[j][0], s[j][1]));
            mx1 = fmaxf(mx1, fmaxf(s[j][2], s[j][3]));
        }
        mx0 = fmaxf(mx0, __shfl_xor_sync(0xffffffffu, mx0, 1));
        mx0 = fmaxf(mx0, __shfl_xor_sync(0xffffffffu, mx0, 2));
        mx1 = fmaxf(mx1, __shfl_xor_sync(0xffffffffu, mx1, 1));
        mx1 = fmaxf(mx1, __shfl_xor_sync(0xffffffffu, mx1, 2));
        float mn0 = fmaxf(m0, mx0), mn1 = fmaxf(m1, mx1);
        float sc0 = __expf(m0 - mn0), sc1 = __expf(m1 - mn1);
        m0 = mn0; m1 = mn1;
        float ls0 = 0.f, ls1 = 0.f;
#pragma unroll
        for (int j = 0; j < 8; j++) {
            s[j][0] = __expf(s[j][0] - m0);
            s[j][1] = __expf(s[j][1] - m0);
            s[j][2] = __expf(s[j][2] - m1);
            s[j][3] = __expf(s[j][3] - m1);
            ls0 += s[j][0] + s[j][1];
            ls1 += s[j][2] + s[j][3];
        }
        ls0 += __shfl_xor_sync(0xffffffffu, ls0, 1);
        ls0 += __shfl_xor_sync(0xffffffffu, ls0, 2);
        ls1 += __shfl_xor_sync(0xffffffffu, ls1, 1);
        ls1 += __shfl_xor_sync(0xffffffffu, ls1, 2);
        l0 = l0 * sc0 + ls0;
        l1 = l1 * sc1 + ls1;
#pragma unroll
        for (int j = 0; j < 8; j++) {
            o[j][0] *= sc0; o[j][1] *= sc0;
            o[j][2] *= sc1; o[j][3] *= sc1;
        }

        // O += P @ V  (P repacked from S fragments in registers)
#pragma unroll
        for (int t = 0; t < 4; t++) {
            uint32_t ph[4], pl[4];
            split_pack2(s[2 * t][0],     s[2 * t][1],     ph[0], pl[0]);
            split_pack2(s[2 * t][2],     s[2 * t][3],     ph[1], pl[1]);
            split_pack2(s[2 * t + 1][0], s[2 * t + 1][1], ph[2], pl[2]);
            split_pack2(s[2 * t + 1][2], s[2 * t + 1][3], ph[3], pl[3]);
#pragma unroll
            for (int g = 0; g < 4; g++) {
                uint32_t eoff = ((g * 16 + b_nof) * AQ_STR + t * 16 + b_kof) * 2;
                uint32_t vh4[4], vl4[4];
                LDSM_X4(vh4[0], vh4[1], vh4[2], vh4[3], vh_b + eoff);
                LDSM_X4(vl4[0], vl4[1], vl4[2], vl4[3], vl_b + eoff);
                MMA_BF16(o[2 * g + 0], ph, vh4[0], vh4[1]);
                MMA_BF16(o[2 * g + 1], ph, vh4[2], vh4[3]);
                MMA_BF16(o[2 * g + 0], ph, vl4[0], vl4[1]);
                MMA_BF16(o[2 * g + 1], ph, vl4[2], vl4[3]);
                MMA_BF16(o[2 * g + 0], pl, vh4[0], vh4[1]);
                MMA_BF16(o[2 * g + 1], pl, vh4[2], vh4[3]);
            }
        }
        __syncthreads();
    }

    // Epilogue: normalize, split, write att (split bf16) [token][h*64+d]
    const float inv0 = 1.0f / l0, inv1 = 1.0f / l1;
    const int b  = bh >> 4;
    const int hh = bh & 15;
    const int r0 = qt * 128 + w * 16 + (lane >> 2);
    const int r1 = r0 + 8;
    const int col0 = hh * HEAD_DIM + ((lane & 3) << 1);
#pragma unroll
    for (int j = 0; j < 8; j++) {
        uint32_t ph, pl;
        size_t o0 = (size_t)(b * N_SEQ + r0) * D_MODEL + col0 + 8 * j;
        split_pack2(o[j][0] * inv0, o[j][1] * inv0, ph, pl);
        *(uint32_t*)&g_att_hi[o0] = ph;
        *(uint32_t*)&g_att_lo[o0] = pl;
        size_t o1 = (size_t)(b * N_SEQ + r1) * D_MODEL + col0 + 8 * j;
        split_pack2(o[j][2] * inv1, o[j][3] * inv1, ph, pl);
        *(uint32_t*)&g_att_hi[o1] = ph;
        *(uint32_t*)&g_att_lo[o1] = pl;
    }
}

// ---------------------------------------------------------------------------
// Launch
// ---------------------------------------------------------------------------
extern "C" void kernel_launch(void* const* d_in, const int* in_sizes, int n_in,
                              void* d_out, int out_size)
{
    const float* x      = (const float*)d_in[0];
    const float* W_qkv  = (const float*)d_in[1];
    const float* b_qkv  = (const float*)d_in[2];
    const float* W_out  = (const float*)d_in[3];
    const float* b_out  = (const float*)d_in[4];
    float* out = (float*)d_out;

    static bf16 *xh = nullptr, *xl, *wqh, *wql, *woh, *wol, *ath, *atl;
    static bool init_done = false;
    if (!init_done) {
        cudaGetSymbolAddress((void**)&xh,  g_x_hi);
        cudaGetSymbolAddress((void**)&xl,  g_x_lo);
        cudaGetSymbolAddress((void**)&wqh, g_wqkv_hi);
        cudaGetSymbolAddress((void**)&wql, g_wqkv_lo);
        cudaGetSymbolAddress((void**)&woh, g_wout_hi);
        cudaGetSymbolAddress((void**)&wol, g_wout_lo);
        cudaGetSymbolAddress((void**)&ath, g_att_hi);
        cudaGetSymbolAddress((void**)&atl, g_att_lo);
        cudaFuncSetAttribute(attn_mma_kernel,
                             cudaFuncAttributeMaxDynamicSharedMemorySize,
                             ATT_SMEM_BYTES);
        init_done = true;
    }

    // 0) split conversions
    {
        int n4 = (TOKENS * D_MODEL) / 4;
        split_x_kernel<<<n4 / 256, 256>>>(x, xh, xl, n4);
        dim3 blk(32, 8);
        split_wt_kernel<<<dim3(QKV_COLS / 32, D_MODEL / 32), blk>>>(W_qkv, wqh, wql, QKV_COLS, D_MODEL);
        split_wt_kernel<<<dim3(D_MODEL / 32, D_MODEL / 32), blk>>>(W_out, woh, wol, D_MODEL, D_MODEL);
    }

    // 1) QKV projection -> split Q/K/Vt
    {
        dim3 grid(QKV_COLS / 128, TOKENS / 128);
        mma_gemm_kernel<<<grid, 256>>>(xh, xl, wqh, wql, b_qkv, nullptr,
                                       TOKENS, QKV_COLS, D_MODEL, 0);
    }

    // 2) Flash attention (mma.sync split-bf16) -> split att
    {
        dim3 grid(N_SEQ / 128, BH);
        attn_mma_kernel<<<grid, 256, ATT_SMEM_BYTES>>>();
    }

    // 3) Output projection -> fp32 out
    {
        dim3 grid(D_MODEL / 128, TOKENS / 128);
        mma_gemm_kernel<<<grid, 256>>>(ath, atl, woh, wol, b_out, out,
                                       TOKENS, D_MODEL, D_MODEL, 1);
    }
}

// round 9
// speedup vs baseline: 3.1010x; 1.3218x over previous
#include <cuda_runtime.h>
#include <cuda_bf16.h>
#include <cstdint>

// Problem constants
#define B_SZ 4
#define N_SEQ 2048
#define D_MODEL 1024
#define N_HEADS 16
#define HEAD_DIM 64
#define BH (B_SZ * N_HEADS)          // 64
#define TOKENS (B_SZ * N_SEQ)        // 8192
#define QKV_COLS (3 * D_MODEL)       // 3072

typedef __nv_bfloat16 bf16;

// ---------------------------------------------------------------------------
// Scratch (module-static device memory; no runtime allocation)
// ---------------------------------------------------------------------------
#define QKV_ELEMS ((size_t)BH * N_SEQ * HEAD_DIM)   // 8388608
__device__ bf16 g_x_hi[(size_t)TOKENS * D_MODEL];
__device__ bf16 g_x_lo[(size_t)TOKENS * D_MODEL];
__device__ bf16 g_wqkv_hi[(size_t)QKV_COLS * D_MODEL];   // [n][k]
__device__ bf16 g_wqkv_lo[(size_t)QKV_COLS * D_MODEL];
__device__ bf16 g_wout_hi[(size_t)D_MODEL * D_MODEL];    // [n][k]
__device__ bf16 g_wout_lo[(size_t)D_MODEL * D_MODEL];
__device__ bf16 g_q_hi[QKV_ELEMS];   // [bh][n][dh], pre-scaled by 0.125
__device__ bf16 g_q_lo[QKV_ELEMS];
__device__ bf16 g_k_hi[QKV_ELEMS];   // [bh][n][dh]
__device__ bf16 g_k_lo[QKV_ELEMS];
__device__ bf16 g_vt_hi[QKV_ELEMS];  // [bh][dh][n]  (transposed)
__device__ bf16 g_vt_lo[QKV_ELEMS];
__device__ bf16 g_att_hi[(size_t)TOKENS * D_MODEL];  // [token][h*64+dh]
__device__ bf16 g_att_lo[(size_t)TOKENS * D_MODEL];

// ---------------------------------------------------------------------------
// Helpers
// ---------------------------------------------------------------------------
__device__ __forceinline__ uint32_t smem_u32(const void* p) {
    uint32_t a;
    asm("{ .reg .u64 t; cvta.to.shared.u64 t, %1; cvt.u32.u64 %0, t; }"
        : "=r"(a) : "l"(p));
    return a;
}

__device__ __forceinline__ void split1(float x, unsigned short& h, unsigned short& l) {
    bf16 bh_ = __float2bfloat16(x);
    float r = x - __bfloat162float(bh_);
    bf16 bl_ = __float2bfloat16(r);
    h = __bfloat16_as_ushort(bh_);
    l = __bfloat16_as_ushort(bl_);
}

__device__ __forceinline__ void split_pack2(float x, float y, uint32_t& hi, uint32_t& lo) {
    unsigned short hx, lx, hy, ly;
    split1(x, hx, lx);
    split1(y, hy, ly);
    hi = (uint32_t)hx | ((uint32_t)hy << 16);
    lo = (uint32_t)lx | ((uint32_t)ly << 16);
}

#define LDSM_X4(r0, r1, r2, r3, addr) \
    asm volatile("ldmatrix.sync.aligned.m8n8.x4.shared.b16 {%0,%1,%2,%3}, [%4];" \
                 : "=r"(r0), "=r"(r1), "=r"(r2), "=r"(r3) : "r"(addr))

#define MMA_BF16(c, a, b0, b1) \
    asm volatile("mma.sync.aligned.m16n8k16.row.col.f32.bf16.bf16.f32 " \
                 "{%0,%1,%2,%3}, {%4,%5,%6,%7}, {%8,%9}, {%0,%1,%2,%3};" \
                 : "+f"((c)[0]), "+f"((c)[1]), "+f"((c)[2]), "+f"((c)[3]) \
                 : "r"((a)[0]), "r"((a)[1]), "r"((a)[2]), "r"((a)[3]), \
                   "r"(b0), "r"(b1))

#define CP16(saddr, gptr) \
    asm volatile("cp.async.cg.shared.global [%0], [%1], 16;" \
                 :: "r"(saddr), "l"(gptr) : "memory")
#define CP_COMMIT() asm volatile("cp.async.commit_group;" ::: "memory")
#define CP_WAIT(n)  asm volatile("cp.async.wait_group %0;" :: "n"(n) : "memory")

// ---------------------------------------------------------------------------
// Conversion kernels
// ---------------------------------------------------------------------------
__global__ void split_x_kernel(const float* __restrict__ x, bf16* __restrict__ hi,
                               bf16* __restrict__ lo, int n4)
{
    int idx = blockIdx.x * 256 + threadIdx.x;
    if (idx >= n4) return;
    float4 v = ((const float4*)x)[idx];
    uint32_t h0, l0, h1, l1;
    split_pack2(v.x, v.y, h0, l0);
    split_pack2(v.z, v.w, h1, l1);
    ((uint2*)hi)[idx] = make_uint2(h0, h1);
    ((uint2*)lo)[idx] = make_uint2(l0, l1);
}

__global__ void split_wt_kernel(const float* __restrict__ W, bf16* __restrict__ hi,
                                bf16* __restrict__ lo, int N, int K)
{
    __shared__ float t[32][33];
    const int tx = threadIdx.x, ty = threadIdx.y;  // block (32,8)
    const int n0 = blockIdx.x * 32, k0 = blockIdx.y * 32;
#pragma unroll
    for (int s = 0; s < 4; s++)
        t[ty + 8 * s][tx] = W[(size_t)(k0 + ty + 8 * s) * N + n0 + tx];
    __syncthreads();
#pragma unroll
    for (int s = 0; s < 4; s++) {
        const int nn = ty + 8 * s, kk = tx;
        float v = t[kk][nn];
        unsigned short h, l;
        split1(v, h, l);
        hi[(size_t)(n0 + nn) * K + k0 + kk] = __ushort_as_bfloat16(h);
        lo[(size_t)(n0 + nn) * K + k0 + kk] = __ushort_as_bfloat16(l);
    }
}

// ---------------------------------------------------------------------------
// Warp-MMA split-bf16 GEMM, cp.async double-buffered.
// C[M,N] = A[M,K] @ Bt[N,K]^T + bias[N].  BM=BN=128, BK=32, 256 thr, 8 warps.
// Dynamic smem: 2 stages x (Ah|Al|Bh|Bl) of 128*SSTRIDE bf16 = 81920 B.
// ---------------------------------------------------------------------------
#define SSTRIDE 40
#define G_ARR_B (128 * SSTRIDE * 2)          // 10240 bytes per array
#define G_STAGE_B (4 * G_ARR_B)              // 40960 bytes per stage
#define G_SMEM_B (2 * G_STAGE_B)             // 81920

__global__ void __launch_bounds__(256, 2)
mma_gemm_kernel(const bf16* __restrict__ Ah_g, const bf16* __restrict__ Al_g,
                const bf16* __restrict__ Bh_g, const bf16* __restrict__ Bl_g,
                const float* __restrict__ bias, float* __restrict__ C,
                int M, int N, int K, int mode)
{
    extern __shared__ __align__(16) char dsm[];
    const uint32_t sb0 = smem_u32(dsm);

    const int tid  = threadIdx.x;
    const int wid  = tid >> 5;
    const int lane = tid & 31;
    const int wr   = wid >> 1;
    const int wc   = wid & 1;

    const int row0 = blockIdx.y * 128;
    const int col0 = blockIdx.x * 128;

    float acc[2][8][4];
#pragma unroll
    for (int i = 0; i < 2; i++)
#pragma unroll
        for (int j = 0; j < 8; j++)
#pragma unroll
            for (int c = 0; c < 4; c++) acc[i][j][c] = 0.f;

    const uint32_t a_row = lane & 15;
    const uint32_t a_kof = (lane >> 4) << 3;
    const uint32_t b_nof = ((lane >> 4) << 3) + (lane & 7);
    const uint32_t b_kof = ((lane >> 3) & 1) << 3;

    // per-thread load coords (2 uint4 rows per array)
    const int f0 = tid, f1 = 256 + tid;
    const int r_0 = f0 >> 2, c8_0 = (f0 & 3) << 3;
    const int r_1 = f1 >> 2, c8_1 = (f1 & 3) << 3;
    const uint32_t so_0 = ((uint32_t)r_0 * SSTRIDE + c8_0) * 2;
    const uint32_t so_1 = ((uint32_t)r_1 * SSTRIDE + c8_1) * 2;

#define G_ISSUE(stage, k0_)                                                     \
    do {                                                                        \
        uint32_t sb = sb0 + (stage) * G_STAGE_B;                                \
        size_t ga0 = (size_t)(row0 + r_0) * K + (k0_) + c8_0;                   \
        size_t ga1 = (size_t)(row0 + r_1) * K + (k0_) + c8_1;                   \
        size_t gb0 = (size_t)(col0 + r_0) * K + (k0_) + c8_0;                   \
        size_t gb1 = (size_t)(col0 + r_1) * K + (k0_) + c8_1;                   \
        CP16(sb + 0 * G_ARR_B + so_0, Ah_g + ga0);                              \
        CP16(sb + 0 * G_ARR_B + so_1, Ah_g + ga1);                              \
        CP16(sb + 1 * G_ARR_B + so_0, Al_g + ga0);                              \
        CP16(sb + 1 * G_ARR_B + so_1, Al_g + ga1);                              \
        CP16(sb + 2 * G_ARR_B + so_0, Bh_g + gb0);                              \
        CP16(sb + 2 * G_ARR_B + so_1, Bh_g + gb1);                              \
        CP16(sb + 3 * G_ARR_B + so_0, Bl_g + gb0);                              \
        CP16(sb + 3 * G_ARR_B + so_1, Bl_g + gb1);                              \
        CP_COMMIT();                                                            \
    } while (0)

    const int niter = K / 32;
    G_ISSUE(0, 0);

    for (int it = 0; it < niter; it++) {
        if (it + 1 < niter) {
            G_ISSUE((it + 1) & 1, (it + 1) * 32);
            CP_WAIT(1);
        } else {
            CP_WAIT(0);
        }
        __syncthreads();

        const uint32_t sb = sb0 + (it & 1) * G_STAGE_B;
        const uint32_t ah_b = sb + 0 * G_ARR_B;
        const uint32_t al_b = sb + 1 * G_ARR_B;
        const uint32_t bh_b = sb + 2 * G_ARR_B;
        const uint32_t bl_b = sb + 3 * G_ARR_B;

#pragma unroll
        for (int ks = 0; ks < 2; ks++) {
            const uint32_t kk = ks * 16;
            uint32_t ahr[2][4], alr[2][4];
#pragma unroll
            for (int i = 0; i < 2; i++) {
                uint32_t eoff = ((wr * 32 + i * 16 + a_row) * SSTRIDE + kk + a_kof) * 2;
                LDSM_X4(ahr[i][0], ahr[i][1], ahr[i][2], ahr[i][3], ah_b + eoff);
                LDSM_X4(alr[i][0], alr[i][1], alr[i][2], alr[i][3], al_b + eoff);
            }
#pragma unroll
            for (int jp = 0; jp < 4; jp++) {
                const uint32_t nb = wc * 64 + jp * 16;
                uint32_t eoff = ((nb + b_nof) * SSTRIDE + kk + b_kof) * 2;
                uint32_t bhr[4], blr[4];
                LDSM_X4(bhr[0], bhr[1], bhr[2], bhr[3], bh_b + eoff);
                LDSM_X4(blr[0], blr[1], blr[2], blr[3], bl_b + eoff);
#pragma unroll
                for (int i = 0; i < 2; i++) {
                    MMA_BF16(acc[i][2 * jp + 0], ahr[i], bhr[0], bhr[1]);
                    MMA_BF16(acc[i][2 * jp + 1], ahr[i], bhr[2], bhr[3]);
                    MMA_BF16(acc[i][2 * jp + 0], ahr[i], blr[0], blr[1]);
                    MMA_BF16(acc[i][2 * jp + 1], ahr[i], blr[2], blr[3]);
                    MMA_BF16(acc[i][2 * jp + 0], alr[i], bhr[0], bhr[1]);
                    MMA_BF16(acc[i][2 * jp + 1], alr[i], bhr[2], bhr[3]);
                }
            }
        }
        __syncthreads();
    }
#undef G_ISSUE

    const int mbase = row0 + wr * 32 + (lane >> 2);
    const int nbase = col0 + wc * 64 + ((lane & 3) << 1);

    if (mode == 0) {
#pragma unroll
        for (int i = 0; i < 2; i++) {
#pragma unroll
            for (int rr = 0; rr < 2; rr++) {
                const int m  = mbase + i * 16 + rr * 8;
                const int bb = m >> 11;
                const int nn = m & 2047;
#pragma unroll
                for (int j = 0; j < 8; j++) {
                    const int jg0 = nbase + j * 8;
                    const int sel = jg0 >> 10;
                    const int hh  = (jg0 >> 6) & 15;
                    const int dh  = jg0 & 63;
                    const int bhd = bb * N_HEADS + hh;
                    float v0 = acc[i][j][rr * 2 + 0] + bias[jg0];
                    float v1 = acc[i][j][rr * 2 + 1] + bias[jg0 + 1];
                    if (sel == 0) { v0 *= 0.125f; v1 *= 0.125f; }
                    uint32_t ph, pl;
                    split_pack2(v0, v1, ph, pl);
                    if (sel == 0) {
                        size_t o = ((size_t)bhd * N_SEQ + nn) * HEAD_DIM + dh;
                        *(uint32_t*)&g_q_hi[o] = ph;
                        *(uint32_t*)&g_q_lo[o] = pl;
                    } else if (sel == 1) {
                        size_t o = ((size_t)bhd * N_SEQ + nn) * HEAD_DIM + dh;
                        *(uint32_t*)&g_k_hi[o] = ph;
                        *(uint32_t*)&g_k_lo[o] = pl;
                    } else {
                        size_t o = ((size_t)bhd * HEAD_DIM + dh) * N_SEQ + nn;
                        g_vt_hi[o] = __ushort_as_bfloat16((unsigned short)(ph & 0xffff));
                        g_vt_lo[o] = __ushort_as_bfloat16((unsigned short)(pl & 0xffff));
                        g_vt_hi[o + N_SEQ] = __ushort_as_bfloat16((unsigned short)(ph >> 16));
                        g_vt_lo[o + N_SEQ] = __ushort_as_bfloat16((unsigned short)(pl >> 16));
                    }
                }
            }
        }
    } else {
#pragma unroll
        for (int i = 0; i < 2; i++) {
#pragma unroll
            for (int rr = 0; rr < 2; rr++) {
                const int m = mbase + i * 16 + rr * 8;
                float* cp = C + (size_t)m * N;
#pragma unroll
                for (int j = 0; j < 8; j++) {
#pragma unroll
                    for (int c = 0; c < 2; c++) {
                        const int jg = nbase + j * 8 + c;
                        cp[jg] = acc[i][j][rr * 2 + c] + bias[jg];
                    }
                }
            }
        }
    }
}

// ---------------------------------------------------------------------------
// mma.sync flash attention, cp.async double-buffered K/V.
// CTA: (head bh, 128-query tile). 8 warps x m16.
// Dynamic smem: Qh|Ql (2 x 18432) + 2 stages x (Kh|Kl|Vh|Vl) (4 x 9216 each)
// ---------------------------------------------------------------------------
#define AQ_STR 72
#define A_Q_ARR_B (128 * AQ_STR * 2)     // 18432
#define A_KV_ARR_B (64 * AQ_STR * 2)     // 9216
#define A_KV_STAGE_B (4 * A_KV_ARR_B)    // 36864
#define A_KV_BASE (2 * A_Q_ARR_B)        // 36864
#define ATT_SMEM_BYTES (A_KV_BASE + 2 * A_KV_STAGE_B)   // 110592

__global__ void __launch_bounds__(256)
attn_mma_kernel()
{
    extern __shared__ __align__(16) char dsm[];
    const uint32_t sb0  = smem_u32(dsm);
    const uint32_t qh_b = sb0;
    const uint32_t ql_b = sb0 + A_Q_ARR_B;

    const int tid  = threadIdx.x;
    const int w    = tid >> 5;
    const int lane = tid & 31;
    const int bh   = blockIdx.y;
    const int qt   = blockIdx.x;

    const bf16* ksrc_h = g_k_hi + (size_t)bh * N_SEQ * HEAD_DIM;
    const bf16* ksrc_l = g_k_lo + (size_t)bh * N_SEQ * HEAD_DIM;
    const bf16* vsrc_h = g_vt_hi + (size_t)bh * HEAD_DIM * N_SEQ;
    const bf16* vsrc_l = g_vt_lo + (size_t)bh * HEAD_DIM * N_SEQ;

    // per-thread KV load coords (2 uint4 per array)
    const int f0 = tid, f1 = 256 + tid;
    const int kr0 = f0 >> 3, kc0 = (f0 & 7) << 3;
    const int kr1 = f1 >> 3, kc1 = (f1 & 7) << 3;
    const uint32_t kso0 = ((uint32_t)kr0 * AQ_STR + kc0) * 2;
    const uint32_t kso1 = ((uint32_t)kr1 * AQ_STR + kc1) * 2;

#define A_ISSUE(stage, kt_)                                                     \
    do {                                                                        \
        uint32_t sb = sb0 + A_KV_BASE + (stage) * A_KV_STAGE_B;                 \
        size_t gk0 = (size_t)((kt_) * 64 + kr0) * HEAD_DIM + kc0;               \
        size_t gk1 = (size_t)((kt_) * 64 + kr1) * HEAD_DIM + kc1;               \
        size_t gv0 = (size_t)kr0 * N_SEQ + (kt_) * 64 + kc0;                    \
        size_t gv1 = (size_t)kr1 * N_SEQ + (kt_) * 64 + kc1;                    \
        CP16(sb + 0 * A_KV_ARR_B + kso0, ksrc_h + gk0);                         \
        CP16(sb + 0 * A_KV_ARR_B + kso1, ksrc_h + gk1);                         \
        CP16(sb + 1 * A_KV_ARR_B + kso0, ksrc_l + gk0);                         \
        CP16(sb + 1 * A_KV_ARR_B + kso1, ksrc_l + gk1);                         \
        CP16(sb + 2 * A_KV_ARR_B + kso0, vsrc_h + gv0);                         \
        CP16(sb + 2 * A_KV_ARR_B + kso1, vsrc_h + gv1);                         \
        CP16(sb + 3 * A_KV_ARR_B + kso0, vsrc_l + gv0);                         \
        CP16(sb + 3 * A_KV_ARR_B + kso1, vsrc_l + gv1);                         \
        CP_COMMIT();                                                            \
    } while (0)

    A_ISSUE(0, 0);

    // Load Q tile [128][64] hi/lo (plain loads, once)
    const bf16* qsrc_h = g_q_hi + ((size_t)bh * N_SEQ + qt * 128) * HEAD_DIM;
    const bf16* qsrc_l = g_q_lo + ((size_t)bh * N_SEQ + qt * 128) * HEAD_DIM;
#pragma unroll
    for (int i = 0; i < 4; i++) {
        int f  = i * 256 + tid;
        int r  = f >> 3;
        int c8 = (f & 7) << 3;
        uint32_t so = ((uint32_t)r * AQ_STR + c8) * 2;
        *(uint4*)(dsm + qh_b - sb0 + so) = *(const uint4*)(qsrc_h + r * HEAD_DIM + c8);
        *(uint4*)(dsm + ql_b - sb0 + so) = *(const uint4*)(qsrc_l + r * HEAD_DIM + c8);
    }
    __syncthreads();

    const uint32_t a_row = lane & 15;
    const uint32_t a_kof = (lane >> 4) << 3;
    const uint32_t b_nof = ((lane >> 4) << 3) + (lane & 7);
    const uint32_t b_kof = ((lane >> 3) & 1) << 3;

    uint32_t qfh[4][4], qfl[4][4];
#pragma unroll
    for (int t = 0; t < 4; t++) {
        uint32_t eoff = ((w * 16 + a_row) * AQ_STR + t * 16 + a_kof) * 2;
        LDSM_X4(qfh[t][0], qfh[t][1], qfh[t][2], qfh[t][3], qh_b + eoff);
        LDSM_X4(qfl[t][0], qfl[t][1], qfl[t][2], qfl[t][3], ql_b + eoff);
    }

    float m0 = -1e30f, m1 = -1e30f, l0 = 0.f, l1 = 0.f;
    float o[8][4];
#pragma unroll
    for (int j = 0; j < 8; j++)
#pragma unroll
        for (int c = 0; c < 4; c++) o[j][c] = 0.f;

    const int nkt = N_SEQ / 64;
    for (int kt = 0; kt < nkt; kt++) {
        if (kt + 1 < nkt) {
            A_ISSUE((kt + 1) & 1, kt + 1);
            CP_WAIT(1);
        } else {
            CP_WAIT(0);
        }
        __syncthreads();

        const uint32_t sb = sb0 + A_KV_BASE + (kt & 1) * A_KV_STAGE_B;
        const uint32_t kh_b = sb + 0 * A_KV_ARR_B;
        const uint32_t kl_b = sb + 1 * A_KV_ARR_B;
        const uint32_t vh_b = sb + 2 * A_KV_ARR_B;
        const uint32_t vl_b = sb + 3 * A_KV_ARR_B;

        // S = Q @ K^T (scale pre-folded into Q)
        float s[8][4];
#pragma unroll
        for (int j = 0; j < 8; j++)
#pragma unroll
            for (int c = 0; c < 4; c++) s[j][c] = 0.f;

#pragma unroll
        for (int t = 0; t < 4; t++) {
#pragma unroll
            for (int g = 0; g < 4; g++) {
                uint32_t eoff = ((g * 16 + b_nof) * AQ_STR + t * 16 + b_kof) * 2;
                uint32_t kh4[4], kl4[4];
                LDSM_X4(kh4[0], kh4[1], kh4[2], kh4[3], kh_b + eoff);
                LDSM_X4(kl4[0], kl4[1], kl4[2], kl4[3], kl_b + eoff);
                MMA_BF16(s[2 * g + 0], qfh[t], kh4[0], kh4[1]);
                MMA_BF16(s[2 * g + 1], qfh[t], kh4[2], kh4[3]);
                MMA_BF16(s[2 * g + 0], qfh[t], kl4[0], kl4[1]);
                MMA_BF16(s[2 * g + 1], qfh[t], kl4[2], kl4[3]);
                MMA_BF16(s[2 * g + 0], qfl[t], kh4[0], kh4[1]);
                MMA_BF16(s[2 * g + 1], qfl[t], kh4[2], kh4[3]);
            }
        }

        // Online softmax
        float mx0 = -1e30f, mx1 = -1e30f;
#pragma unroll
        for (int j = 0; j < 8; j++) {
            mx0 = fmaxf(mx0, fmaxf(s[j][0], s[j][1]));
            mx1 = fmaxf(mx1, fmaxf(s[j][2], s[j][3]));
        }
        mx0 = fmaxf(mx0, __shfl_xor_sync(0xffffffffu, mx0, 1));
        mx0 = fmaxf(mx0, __shfl_xor_sync(0xffffffffu, mx0, 2));
        mx1 = fmaxf(mx1, __shfl_xor_sync(0xffffffffu, mx1, 1));
        mx1 = fmaxf(mx1, __shfl_xor_sync(0xffffffffu, mx1, 2));
        float mn0 = fmaxf(m0, mx0), mn1 = fmaxf(m1, mx1);
        float sc0 = __expf(m0 - mn0), sc1 = __expf(m1 - mn1);
        m0 = mn0; m1 = mn1;
        float ls0 = 0.f, ls1 = 0.f;
#pragma unroll
        for (int j = 0; j < 8; j++) {
            s[j][0] = __expf(s[j][0] - m0);
            s[j][1] = __expf(s[j][1] - m0);
            s[j][2] = __expf(s[j][2] - m1);
            s[j][3] = __expf(s[j][3] - m1);
            ls0 += s[j][0] + s[j][1];
            ls1 += s[j][2] + s[j][3];
        }
        ls0 += __shfl_xor_sync(0xffffffffu, ls0, 1);
        ls0 += __shfl_xor_sync(0xffffffffu, ls0, 2);
        ls1 += __shfl_xor_sync(0xffffffffu, ls1, 1);
        ls1 += __shfl_xor_sync(0xffffffffu, ls1, 2);
        l0 = l0 * sc0 + ls0;
        l1 = l1 * sc1 + ls1;
#pragma unroll
        for (int j = 0; j < 8; j++) {
            o[j][0] *= sc0; o[j][1] *= sc0;
            o[j][2] *= sc1; o[j][3] *= sc1;
        }

        // O += P @ V  (P repacked from S fragments in registers)
#pragma unroll
        for (int t = 0; t < 4; t++) {
            uint32_t ph[4], pl[4];
            split_pack2(s[2 * t][0],     s[2 * t][1],     ph[0], pl[0]);
            split_pack2(s[2 * t][2],     s[2 * t][3],     ph[1], pl[1]);
            split_pack2(s[2 * t + 1][0], s[2 * t + 1][1], ph[2], pl[2]);
            split_pack2(s[2 * t + 1][2], s[2 * t + 1][3], ph[3], pl[3]);
#pragma unroll
            for (int g = 0; g < 4; g++) {
                uint32_t eoff = ((g * 16 + b_nof) * AQ_STR + t * 16 + b_kof) * 2;
                uint32_t vh4[4], vl4[4];
                LDSM_X4(vh4[0], vh4[1], vh4[2], vh4[3], vh_b + eoff);
                LDSM_X4(vl4[0], vl4[1], vl4[2], vl4[3], vl_b + eoff);
                MMA_BF16(o[2 * g + 0], ph, vh4[0], vh4[1]);
                MMA_BF16(o[2 * g + 1], ph, vh4[2], vh4[3]);
                MMA_BF16(o[2 * g + 0], ph, vl4[0], vl4[1]);
                MMA_BF16(o[2 * g + 1], ph, vl4[2], vl4[3]);
                MMA_BF16(o[2 * g + 0], pl, vh4[0], vh4[1]);
                MMA_BF16(o[2 * g + 1], pl, vh4[2], vh4[3]);
            }
        }
        __syncthreads();
    }
#undef A_ISSUE

    // Epilogue: normalize, split, write att (split bf16) [token][h*64+d]
    const float inv0 = 1.0f / l0, inv1 = 1.0f / l1;
    const int b  = bh >> 4;
    const int hh = bh & 15;
    const int r0 = qt * 128 + w * 16 + (lane >> 2);
    const int r1 = r0 + 8;
    const int col0 = hh * HEAD_DIM + ((lane & 3) << 1);
#pragma unroll
    for (int j = 0; j < 8; j++) {
        uint32_t ph, pl;
        size_t o0 = (size_t)(b * N_SEQ + r0) * D_MODEL + col0 + 8 * j;
        split_pack2(o[j][0] * inv0, o[j][1] * inv0, ph, pl);
        *(uint32_t*)&g_att_hi[o0] = ph;
        *(uint32_t*)&g_att_lo[o0] = pl;
        size_t o1 = (size_t)(b * N_SEQ + r1) * D_MODEL + col0 + 8 * j;
        split_pack2(o[j][2] * inv1, o[j][3] * inv1, ph, pl);
        *(uint32_t*)&g_att_hi[o1] = ph;
        *(uint32_t*)&g_att_lo[o1] = pl;
    }
}

// ---------------------------------------------------------------------------
// Launch
// ---------------------------------------------------------------------------
extern "C" void kernel_launch(void* const* d_in, const int* in_sizes, int n_in,
                              void* d_out, int out_size)
{
    const float* x      = (const float*)d_in[0];
    const float* W_qkv  = (const float*)d_in[1];
    const float* b_qkv  = (const float*)d_in[2];
    const float* W_out  = (const float*)d_in[3];
    const float* b_out  = (const float*)d_in[4];
    float* out = (float*)d_out;

    static bf16 *xh = nullptr, *xl, *wqh, *wql, *woh, *wol, *ath, *atl;
    static bool init_done = false;
    if (!init_done) {
        cudaGetSymbolAddress((void**)&xh,  g_x_hi);
        cudaGetSymbolAddress((void**)&xl,  g_x_lo);
        cudaGetSymbolAddress((void**)&wqh, g_wqkv_hi);
        cudaGetSymbolAddress((void**)&wql, g_wqkv_lo);
        cudaGetSymbolAddress((void**)&woh, g_wout_hi);
        cudaGetSymbolAddress((void**)&wol, g_wout_lo);
        cudaGetSymbolAddress((void**)&ath, g_att_hi);
        cudaGetSymbolAddress((void**)&atl, g_att_lo);
        cudaFuncSetAttribute(mma_gemm_kernel,
                             cudaFuncAttributeMaxDynamicSharedMemorySize,
                             G_SMEM_B);
        cudaFuncSetAttribute(attn_mma_kernel,
                             cudaFuncAttributeMaxDynamicSharedMemorySize,
                             ATT_SMEM_BYTES);
        init_done = true;
    }

    // 0) split conversions
    {
        int n4 = (TOKENS * D_MODEL) / 4;
        split_x_kernel<<<n4 / 256, 256>>>(x, xh, xl, n4);
        dim3 blk(32, 8);
        split_wt_kernel<<<dim3(QKV_COLS / 32, D_MODEL / 32), blk>>>(W_qkv, wqh, wql, QKV_COLS, D_MODEL);
        split_wt_kernel<<<dim3(D_MODEL / 32, D_MODEL / 32), blk>>>(W_out, woh, wol, D_MODEL, D_MODEL);
    }

    // 1) QKV projection -> split Q/K/Vt
    {
        dim3 grid(QKV_COLS / 128, TOKENS / 128);
        mma_gemm_kernel<<<grid, 256, G_SMEM_B>>>(xh, xl, wqh, wql, b_qkv, nullptr,
                                                 TOKENS, QKV_COLS, D_MODEL, 0);
    }

    // 2) Flash attention (mma.sync split-bf16, cp.async) -> split att
    {
        dim3 grid(N_SEQ / 128, BH);
        attn_mma_kernel<<<grid, 256, ATT_SMEM_BYTES>>>();
    }

    // 3) Output projection -> fp32 out
    {
        dim3 grid(D_MODEL / 128, TOKENS / 128);
        mma_gemm_kernel<<<grid, 256, G_SMEM_B>>>(ath, atl, woh, wol, b_out, out,
                                                 TOKENS, D_MODEL, D_MODEL, 1);
    }
}

// round 10
// speedup vs baseline: 3.2110x; 1.0355x over previous
#include <cuda_runtime.h>
#include <cuda_bf16.h>
#include <cstdint>

// Problem constants
#define B_SZ 4
#define N_SEQ 2048
#define D_MODEL 1024
#define N_HEADS 16
#define HEAD_DIM 64
#define BH (B_SZ * N_HEADS)          // 64
#define TOKENS (B_SZ * N_SEQ)        // 8192
#define QKV_COLS (3 * D_MODEL)       // 3072

typedef __nv_bfloat16 bf16;

// ---------------------------------------------------------------------------
// Scratch (module-static device memory; no runtime allocation)
// ---------------------------------------------------------------------------
#define QKV_ELEMS ((size_t)BH * N_SEQ * HEAD_DIM)   // 8388608
__device__ bf16 g_x_hi[(size_t)TOKENS * D_MODEL];
__device__ bf16 g_x_lo[(size_t)TOKENS * D_MODEL];
__device__ bf16 g_wqkv_hi[(size_t)QKV_COLS * D_MODEL];   // [n][k]
__device__ bf16 g_wqkv_lo[(size_t)QKV_COLS * D_MODEL];
__device__ bf16 g_wout_hi[(size_t)D_MODEL * D_MODEL];    // [n][k]
__device__ bf16 g_wout_lo[(size_t)D_MODEL * D_MODEL];
__device__ bf16 g_q_hi[QKV_ELEMS];   // [bh][n][dh], pre-scaled by 0.125
__device__ bf16 g_q_lo[QKV_ELEMS];
__device__ bf16 g_k_hi[QKV_ELEMS];   // [bh][n][dh]
__device__ bf16 g_k_lo[QKV_ELEMS];
__device__ bf16 g_vt_hi[QKV_ELEMS];  // [bh][dh][n]  (transposed)
__device__ bf16 g_vt_lo[QKV_ELEMS];
__device__ bf16 g_att_hi[(size_t)TOKENS * D_MODEL];  // [token][h*64+dh]
__device__ bf16 g_att_lo[(size_t)TOKENS * D_MODEL];

// ---------------------------------------------------------------------------
// Helpers
// ---------------------------------------------------------------------------
__device__ __forceinline__ uint32_t smem_u32(const void* p) {
    uint32_t a;
    asm("{ .reg .u64 t; cvta.to.shared.u64 t, %1; cvt.u32.u64 %0, t; }"
        : "=r"(a) : "l"(p));
    return a;
}

__device__ __forceinline__ void split1(float x, unsigned short& h, unsigned short& l) {
    bf16 bh_ = __float2bfloat16(x);
    float r = x - __bfloat162float(bh_);
    bf16 bl_ = __float2bfloat16(r);
    h = __bfloat16_as_ushort(bh_);
    l = __bfloat16_as_ushort(bl_);
}

__device__ __forceinline__ void split_pack2(float x, float y, uint32_t& hi, uint32_t& lo) {
    unsigned short hx, lx, hy, ly;
    split1(x, hx, lx);
    split1(y, hy, ly);
    hi = (uint32_t)hx | ((uint32_t)hy << 16);
    lo = (uint32_t)lx | ((uint32_t)ly << 16);
}

#define LDSM_X4(r0, r1, r2, r3, addr) \
    asm volatile("ldmatrix.sync.aligned.m8n8.x4.shared.b16 {%0,%1,%2,%3}, [%4];" \
                 : "=r"(r0), "=r"(r1), "=r"(r2), "=r"(r3) : "r"(addr))

#define MMA_BF16(c, a, b0, b1) \
    asm volatile("mma.sync.aligned.m16n8k16.row.col.f32.bf16.bf16.f32 " \
                 "{%0,%1,%2,%3}, {%4,%5,%6,%7}, {%8,%9}, {%0,%1,%2,%3};" \
                 : "+f"((c)[0]), "+f"((c)[1]), "+f"((c)[2]), "+f"((c)[3]) \
                 : "r"((a)[0]), "r"((a)[1]), "r"((a)[2]), "r"((a)[3]), \
                   "r"(b0), "r"(b1))

#define CP16(saddr, gptr) \
    asm volatile("cp.async.cg.shared.global [%0], [%1], 16;" \
                 :: "r"(saddr), "l"(gptr) : "memory")
#define CP_COMMIT() asm volatile("cp.async.commit_group;" ::: "memory")
#define CP_WAIT(n)  asm volatile("cp.async.wait_group %0;" :: "n"(n) : "memory")

// ---------------------------------------------------------------------------
// Conversion kernels
// ---------------------------------------------------------------------------
__global__ void split_x_kernel(const float* __restrict__ x, bf16* __restrict__ hi,
                               bf16* __restrict__ lo, int n4)
{
    int idx = blockIdx.x * 256 + threadIdx.x;
    if (idx >= n4) return;
    float4 v = ((const float4*)x)[idx];
    uint32_t h0, l0, h1, l1;
    split_pack2(v.x, v.y, h0, l0);
    split_pack2(v.z, v.w, h1, l1);
    ((uint2*)hi)[idx] = make_uint2(h0, h1);
    ((uint2*)lo)[idx] = make_uint2(l0, l1);
}

__global__ void split_wt_kernel(const float* __restrict__ W, bf16* __restrict__ hi,
                                bf16* __restrict__ lo, int N, int K)
{
    __shared__ float t[32][33];
    const int tx = threadIdx.x, ty = threadIdx.y;  // block (32,8)
    const int n0 = blockIdx.x * 32, k0 = blockIdx.y * 32;
#pragma unroll
    for (int s = 0; s < 4; s++)
        t[ty + 8 * s][tx] = W[(size_t)(k0 + ty + 8 * s) * N + n0 + tx];
    __syncthreads();
#pragma unroll
    for (int s = 0; s < 4; s++) {
        const int nn = ty + 8 * s, kk = tx;
        float v = t[kk][nn];
        unsigned short h, l;
        split1(v, h, l);
        hi[(size_t)(n0 + nn) * K + k0 + kk] = __ushort_as_bfloat16(h);
        lo[(size_t)(n0 + nn) * K + k0 + kk] = __ushort_as_bfloat16(l);
    }
}

// ---------------------------------------------------------------------------
// Warp-MMA split-bf16 GEMM, cp.async double-buffered.
// C[M,N] = A[M,K] @ Bt[N,K]^T + bias[N].  BM=BN=128, BK=32, 256 thr, 8 warps.
// ---------------------------------------------------------------------------
#define SSTRIDE 40
#define G_ARR_B (128 * SSTRIDE * 2)          // 10240 bytes per array
#define G_STAGE_B (4 * G_ARR_B)              // 40960 bytes per stage
#define G_SMEM_B (2 * G_STAGE_B)             // 81920

__global__ void __launch_bounds__(256, 2)
mma_gemm_kernel(const bf16* __restrict__ Ah_g, const bf16* __restrict__ Al_g,
                const bf16* __restrict__ Bh_g, const bf16* __restrict__ Bl_g,
                const float* __restrict__ bias, float* __restrict__ C,
                int M, int N, int K, int mode)
{
    extern __shared__ __align__(16) char dsm[];
    const uint32_t sb0 = smem_u32(dsm);

    const int tid  = threadIdx.x;
    const int wid  = tid >> 5;
    const int lane = tid & 31;
    const int wr   = wid >> 1;
    const int wc   = wid & 1;

    const int row0 = blockIdx.y * 128;
    const int col0 = blockIdx.x * 128;

    float acc[2][8][4];
#pragma unroll
    for (int i = 0; i < 2; i++)
#pragma unroll
        for (int j = 0; j < 8; j++)
#pragma unroll
            for (int c = 0; c < 4; c++) acc[i][j][c] = 0.f;

    const uint32_t a_row = lane & 15;
    const uint32_t a_kof = (lane >> 4) << 3;
    const uint32_t b_nof = ((lane >> 4) << 3) + (lane & 7);
    const uint32_t b_kof = ((lane >> 3) & 1) << 3;

    const int f0 = tid, f1 = 256 + tid;
    const int r_0 = f0 >> 2, c8_0 = (f0 & 3) << 3;
    const int r_1 = f1 >> 2, c8_1 = (f1 & 3) << 3;
    const uint32_t so_0 = ((uint32_t)r_0 * SSTRIDE + c8_0) * 2;
    const uint32_t so_1 = ((uint32_t)r_1 * SSTRIDE + c8_1) * 2;

#define G_ISSUE(stage, k0_)                                                     \
    do {                                                                        \
        uint32_t sb = sb0 + (stage) * G_STAGE_B;                                \
        size_t ga0 = (size_t)(row0 + r_0) * K + (k0_) + c8_0;                   \
        size_t ga1 = (size_t)(row0 + r_1) * K + (k0_) + c8_1;                   \
        size_t gb0 = (size_t)(col0 + r_0) * K + (k0_) + c8_0;                   \
        size_t gb1 = (size_t)(col0 + r_1) * K + (k0_) + c8_1;                   \
        CP16(sb + 0 * G_ARR_B + so_0, Ah_g + ga0);                              \
        CP16(sb + 0 * G_ARR_B + so_1, Ah_g + ga1);                              \
        CP16(sb + 1 * G_ARR_B + so_0, Al_g + ga0);                              \
        CP16(sb + 1 * G_ARR_B + so_1, Al_g + ga1);                              \
        CP16(sb + 2 * G_ARR_B + so_0, Bh_g + gb0);                              \
        CP16(sb + 2 * G_ARR_B + so_1, Bh_g + gb1);                              \
        CP16(sb + 3 * G_ARR_B + so_0, Bl_g + gb0);                              \
        CP16(sb + 3 * G_ARR_B + so_1, Bl_g + gb1);                              \
        CP_COMMIT();                                                            \
    } while (0)

    const int niter = K / 32;
    G_ISSUE(0, 0);

    for (int it = 0; it < niter; it++) {
        if (it + 1 < niter) {
            G_ISSUE((it + 1) & 1, (it + 1) * 32);
            CP_WAIT(1);
        } else {
            CP_WAIT(0);
        }
        __syncthreads();

        const uint32_t sb = sb0 + (it & 1) * G_STAGE_B;
        const uint32_t ah_b = sb + 0 * G_ARR_B;
        const uint32_t al_b = sb + 1 * G_ARR_B;
        const uint32_t bh_b = sb + 2 * G_ARR_B;
        const uint32_t bl_b = sb + 3 * G_ARR_B;

#pragma unroll
        for (int ks = 0; ks < 2; ks++) {
            const uint32_t kk = ks * 16;
            uint32_t ahr[2][4], alr[2][4];
#pragma unroll
            for (int i = 0; i < 2; i++) {
                uint32_t eoff = ((wr * 32 + i * 16 + a_row) * SSTRIDE + kk + a_kof) * 2;
                LDSM_X4(ahr[i][0], ahr[i][1], ahr[i][2], ahr[i][3], ah_b + eoff);
                LDSM_X4(alr[i][0], alr[i][1], alr[i][2], alr[i][3], al_b + eoff);
            }
#pragma unroll
            for (int jp = 0; jp < 4; jp++) {
                const uint32_t nb = wc * 64 + jp * 16;
                uint32_t eoff = ((nb + b_nof) * SSTRIDE + kk + b_kof) * 2;
                uint32_t bhr[4], blr[4];
                LDSM_X4(bhr[0], bhr[1], bhr[2], bhr[3], bh_b + eoff);
                LDSM_X4(blr[0], blr[1], blr[2], blr[3], bl_b + eoff);
#pragma unroll
                for (int i = 0; i < 2; i++) {
                    MMA_BF16(acc[i][2 * jp + 0], ahr[i], bhr[0], bhr[1]);
                    MMA_BF16(acc[i][2 * jp + 1], ahr[i], bhr[2], bhr[3]);
                    MMA_BF16(acc[i][2 * jp + 0], ahr[i], blr[0], blr[1]);
                    MMA_BF16(acc[i][2 * jp + 1], ahr[i], blr[2], blr[3]);
                    MMA_BF16(acc[i][2 * jp + 0], alr[i], bhr[0], bhr[1]);
                    MMA_BF16(acc[i][2 * jp + 1], alr[i], bhr[2], bhr[3]);
                }
            }
        }
        __syncthreads();
    }
#undef G_ISSUE

    const int mbase = row0 + wr * 32 + (lane >> 2);
    const int nbase = col0 + wc * 64 + ((lane & 3) << 1);

    if (mode == 0) {
#pragma unroll
        for (int i = 0; i < 2; i++) {
#pragma unroll
            for (int rr = 0; rr < 2; rr++) {
                const int m  = mbase + i * 16 + rr * 8;
                const int bb = m >> 11;
                const int nn = m & 2047;
#pragma unroll
                for (int j = 0; j < 8; j++) {
                    const int jg0 = nbase + j * 8;
                    const int sel = jg0 >> 10;
                    const int hh  = (jg0 >> 6) & 15;
                    const int dh  = jg0 & 63;
                    const int bhd = bb * N_HEADS + hh;
                    float v0 = acc[i][j][rr * 2 + 0] + bias[jg0];
                    float v1 = acc[i][j][rr * 2 + 1] + bias[jg0 + 1];
                    if (sel == 0) { v0 *= 0.125f; v1 *= 0.125f; }
                    uint32_t ph, pl;
                    split_pack2(v0, v1, ph, pl);
                    if (sel == 0) {
                        size_t o = ((size_t)bhd * N_SEQ + nn) * HEAD_DIM + dh;
                        *(uint32_t*)&g_q_hi[o] = ph;
                        *(uint32_t*)&g_q_lo[o] = pl;
                    } else if (sel == 1) {
                        size_t o = ((size_t)bhd * N_SEQ + nn) * HEAD_DIM + dh;
                        *(uint32_t*)&g_k_hi[o] = ph;
                        *(uint32_t*)&g_k_lo[o] = pl;
                    } else {
                        size_t o = ((size_t)bhd * HEAD_DIM + dh) * N_SEQ + nn;
                        g_vt_hi[o] = __ushort_as_bfloat16((unsigned short)(ph & 0xffff));
                        g_vt_lo[o] = __ushort_as_bfloat16((unsigned short)(pl & 0xffff));
                        g_vt_hi[o + N_SEQ] = __ushort_as_bfloat16((unsigned short)(ph >> 16));
                        g_vt_lo[o + N_SEQ] = __ushort_as_bfloat16((unsigned short)(pl >> 16));
                    }
                }
            }
        }
    } else {
#pragma unroll
        for (int i = 0; i < 2; i++) {
#pragma unroll
            for (int rr = 0; rr < 2; rr++) {
                const int m = mbase + i * 16 + rr * 8;
                float* cp = C + (size_t)m * N;
#pragma unroll
                for (int j = 0; j < 8; j++) {
#pragma unroll
                    for (int c = 0; c < 2; c++) {
                        const int jg = nbase + j * 8 + c;
                        cp[jg] = acc[i][j][rr * 2 + c] + bias[jg];
                    }
                }
            }
        }
    }
}

// ---------------------------------------------------------------------------
// mma.sync flash attention, cp.async double-buffered K/V, 2 CTAs/SM.
// CTA: (head bh, 128-query tile). 8 warps x m16.
// Q fragments are re-loaded from smem each iteration (register relief so that
// __launch_bounds__(256,2) holds without spills).
// ---------------------------------------------------------------------------
#define AQ_STR 72
#define A_Q_ARR_B (128 * AQ_STR * 2)     // 18432
#define A_KV_ARR_B (64 * AQ_STR * 2)     // 9216
#define A_KV_STAGE_B (4 * A_KV_ARR_B)    // 36864
#define A_KV_BASE (2 * A_Q_ARR_B)        // 36864
#define ATT_SMEM_BYTES (A_KV_BASE + 2 * A_KV_STAGE_B)   // 110592

__global__ void __launch_bounds__(256, 2)
attn_mma_kernel()
{
    extern __shared__ __align__(16) char dsm[];
    const uint32_t sb0  = smem_u32(dsm);
    const uint32_t qh_b = sb0;
    const uint32_t ql_b = sb0 + A_Q_ARR_B;

    const int tid  = threadIdx.x;
    const int w    = tid >> 5;
    const int lane = tid & 31;
    const int bh   = blockIdx.y;
    const int qt   = blockIdx.x;

    const bf16* ksrc_h = g_k_hi + (size_t)bh * N_SEQ * HEAD_DIM;
    const bf16* ksrc_l = g_k_lo + (size_t)bh * N_SEQ * HEAD_DIM;
    const bf16* vsrc_h = g_vt_hi + (size_t)bh * HEAD_DIM * N_SEQ;
    const bf16* vsrc_l = g_vt_lo + (size_t)bh * HEAD_DIM * N_SEQ;

    const int f0 = tid, f1 = 256 + tid;
    const int kr0 = f0 >> 3, kc0 = (f0 & 7) << 3;
    const int kr1 = f1 >> 3, kc1 = (f1 & 7) << 3;
    const uint32_t kso0 = ((uint32_t)kr0 * AQ_STR + kc0) * 2;
    const uint32_t kso1 = ((uint32_t)kr1 * AQ_STR + kc1) * 2;

#define A_ISSUE(stage, kt_)                                                     \
    do {                                                                        \
        uint32_t sb = sb0 + A_KV_BASE + (stage) * A_KV_STAGE_B;                 \
        size_t gk0 = (size_t)((kt_) * 64 + kr0) * HEAD_DIM + kc0;               \
        size_t gk1 = (size_t)((kt_) * 64 + kr1) * HEAD_DIM + kc1;               \
        size_t gv0 = (size_t)kr0 * N_SEQ + (kt_) * 64 + kc0;                    \
        size_t gv1 = (size_t)kr1 * N_SEQ + (kt_) * 64 + kc1;                    \
        CP16(sb + 0 * A_KV_ARR_B + kso0, ksrc_h + gk0);                         \
        CP16(sb + 0 * A_KV_ARR_B + kso1, ksrc_h + gk1);                         \
        CP16(sb + 1 * A_KV_ARR_B + kso0, ksrc_l + gk0);                         \
        CP16(sb + 1 * A_KV_ARR_B + kso1, ksrc_l + gk1);                         \
        CP16(sb + 2 * A_KV_ARR_B + kso0, vsrc_h + gv0);                         \
        CP16(sb + 2 * A_KV_ARR_B + kso1, vsrc_h + gv1);                         \
        CP16(sb + 3 * A_KV_ARR_B + kso0, vsrc_l + gv0);                         \
        CP16(sb + 3 * A_KV_ARR_B + kso1, vsrc_l + gv1);                         \
        CP_COMMIT();                                                            \
    } while (0)

    A_ISSUE(0, 0);

    // Load Q tile [128][64] hi/lo (plain loads, once)
    const bf16* qsrc_h = g_q_hi + ((size_t)bh * N_SEQ + qt * 128) * HEAD_DIM;
    const bf16* qsrc_l = g_q_lo + ((size_t)bh * N_SEQ + qt * 128) * HEAD_DIM;
#pragma unroll
    for (int i = 0; i < 4; i++) {
        int f  = i * 256 + tid;
        int r  = f >> 3;
        int c8 = (f & 7) << 3;
        uint32_t so = ((uint32_t)r * AQ_STR + c8) * 2;
        *(uint4*)(dsm + (qh_b - sb0) + so) = *(const uint4*)(qsrc_h + r * HEAD_DIM + c8);
        *(uint4*)(dsm + (ql_b - sb0) + so) = *(const uint4*)(qsrc_l + r * HEAD_DIM + c8);
    }
    __syncthreads();

    const uint32_t a_row = lane & 15;
    const uint32_t a_kof = (lane >> 4) << 3;
    const uint32_t b_nof = ((lane >> 4) << 3) + (lane & 7);
    const uint32_t b_kof = ((lane >> 3) & 1) << 3;

    float m0 = -1e30f, m1 = -1e30f, l0 = 0.f, l1 = 0.f;
    float o[8][4];
#pragma unroll
    for (int j = 0; j < 8; j++)
#pragma unroll
        for (int c = 0; c < 4; c++) o[j][c] = 0.f;

    const int nkt = N_SEQ / 64;
    for (int kt = 0; kt < nkt; kt++) {
        if (kt + 1 < nkt) {
            A_ISSUE((kt + 1) & 1, kt + 1);
            CP_WAIT(1);
        } else {
            CP_WAIT(0);
        }
        __syncthreads();

        const uint32_t sb = sb0 + A_KV_BASE + (kt & 1) * A_KV_STAGE_B;
        const uint32_t kh_b = sb + 0 * A_KV_ARR_B;
        const uint32_t kl_b = sb + 1 * A_KV_ARR_B;
        const uint32_t vh_b = sb + 2 * A_KV_ARR_B;
        const uint32_t vl_b = sb + 3 * A_KV_ARR_B;

        // S = Q @ K^T (scale pre-folded into Q); Q frags re-loaded per t
        float s[8][4];
#pragma unroll
        for (int j = 0; j < 8; j++)
#pragma unroll
            for (int c = 0; c < 4; c++) s[j][c] = 0.f;

#pragma unroll
        for (int t = 0; t < 4; t++) {
            uint32_t qh4[4], ql4[4];
            {
                uint32_t eoff = ((w * 16 + a_row) * AQ_STR + t * 16 + a_kof) * 2;
                LDSM_X4(qh4[0], qh4[1], qh4[2], qh4[3], qh_b + eoff);
                LDSM_X4(ql4[0], ql4[1], ql4[2], ql4[3], ql_b + eoff);
            }
#pragma unroll
            for (int g = 0; g < 4; g++) {
                uint32_t eoff = ((g * 16 + b_nof) * AQ_STR + t * 16 + b_kof) * 2;
                uint32_t kh4[4], kl4[4];
                LDSM_X4(kh4[0], kh4[1], kh4[2], kh4[3], kh_b + eoff);
                LDSM_X4(kl4[0], kl4[1], kl4[2], kl4[3], kl_b + eoff);
                MMA_BF16(s[2 * g + 0], qh4, kh4[0], kh4[1]);
                MMA_BF16(s[2 * g + 1], qh4, kh4[2], kh4[3]);
                MMA_BF16(s[2 * g + 0], qh4, kl4[0], kl4[1]);
                MMA_BF16(s[2 * g + 1], qh4, kl4[2], kl4[3]);
                MMA_BF16(s[2 * g + 0], ql4, kh4[0], kh4[1]);
                MMA_BF16(s[2 * g + 1], ql4, kh4[2], kh4[3]);
            }
        }

        // Online softmax
        float mx0 = -1e30f, mx1 = -1e30f;
#pragma unroll
        for (int j = 0; j < 8; j++) {
            mx0 = fmaxf(mx0, fmaxf(s[j][0], s[j][1]));
            mx1 = fmaxf(mx1, fmaxf(s[j][2], s[j][3]));
        }
        mx0 = fmaxf(mx0, __shfl_xor_sync(0xffffffffu, mx0, 1));
        mx0 = fmaxf(mx0, __shfl_xor_sync(0xffffffffu, mx0, 2));
        mx1 = fmaxf(mx1, __shfl_xor_sync(0xffffffffu, mx1, 1));
        mx1 = fmaxf(mx1, __shfl_xor_sync(0xffffffffu, mx1, 2));
        float mn0 = fmaxf(m0, mx0), mn1 = fmaxf(m1, mx1);
        float sc0 = __expf(m0 - mn0), sc1 = __expf(m1 - mn1);
        m0 = mn0; m1 = mn1;
        float ls0 = 0.f, ls1 = 0.f;
#pragma unroll
        for (int j = 0; j < 8; j++) {
            s[j][0] = __expf(s[j][0] - m0);
            s[j][1] = __expf(s[j][1] - m0);
            s[j][2] = __expf(s[j][2] - m1);
            s[j][3] = __expf(s[j][3] - m1);
            ls0 += s[j][0] + s[j][1];
            ls1 += s[j][2] + s[j][3];
        }
        ls0 += __shfl_xor_sync(0xffffffffu, ls0, 1);
        ls0 += __shfl_xor_sync(0xffffffffu, ls0, 2);
        ls1 += __shfl_xor_sync(0xffffffffu, ls1, 1);
        ls1 += __shfl_xor_sync(0xffffffffu, ls1, 2);
        l0 = l0 * sc0 + ls0;
        l1 = l1 * sc1 + ls1;
#pragma unroll
        for (int j = 0; j < 8; j++) {
            o[j][0] *= sc0; o[j][1] *= sc0;
            o[j][2] *= sc1; o[j][3] *= sc1;
        }

        // O += P @ V  (P repacked from S fragments in registers)
#pragma unroll
        for (int t = 0; t < 4; t++) {
            uint32_t ph[4], pl[4];
            split_pack2(s[2 * t][0],     s[2 * t][1],     ph[0], pl[0]);
            split_pack2(s[2 * t][2],     s[2 * t][3],     ph[1], pl[1]);
            split_pack2(s[2 * t + 1][0], s[2 * t + 1][1], ph[2], pl[2]);
            split_pack2(s[2 * t + 1][2], s[2 * t + 1][3], ph[3], pl[3]);
#pragma unroll
            for (int g = 0; g < 4; g++) {
                uint32_t eoff = ((g * 16 + b_nof) * AQ_STR + t * 16 + b_kof) * 2;
                uint32_t vh4[4], vl4[4];
                LDSM_X4(vh4[0], vh4[1], vh4[2], vh4[3], vh_b + eoff);
                LDSM_X4(vl4[0], vl4[1], vl4[2], vl4[3], vl_b + eoff);
                MMA_BF16(o[2 * g + 0], ph, vh4[0], vh4[1]);
                MMA_BF16(o[2 * g + 1], ph, vh4[2], vh4[3]);
                MMA_BF16(o[2 * g + 0], ph, vl4[0], vl4[1]);
                MMA_BF16(o[2 * g + 1], ph, vl4[2], vl4[3]);
                MMA_BF16(o[2 * g + 0], pl, vh4[0], vh4[1]);
                MMA_BF16(o[2 * g + 1], pl, vh4[2], vh4[3]);
            }
        }
        __syncthreads();
    }
#undef A_ISSUE

    // Epilogue: normalize, split, write att (split bf16) [token][h*64+d]
    const float inv0 = 1.0f / l0, inv1 = 1.0f / l1;
    const int b  = bh >> 4;
    const int hh = bh & 15;
    const int r0 = qt * 128 + w * 16 + (lane >> 2);
    const int r1 = r0 + 8;
    const int col0 = hh * HEAD_DIM + ((lane & 3) << 1);
#pragma unroll
    for (int j = 0; j < 8; j++) {
        uint32_t ph, pl;
        size_t o0 = (size_t)(b * N_SEQ + r0) * D_MODEL + col0 + 8 * j;
        split_pack2(o[j][0] * inv0, o[j][1] * inv0, ph, pl);
        *(uint32_t*)&g_att_hi[o0] = ph;
        *(uint32_t*)&g_att_lo[o0] = pl;
        size_t o1 = (size_t)(b * N_SEQ + r1) * D_MODEL + col0 + 8 * j;
        split_pack2(o[j][2] * inv1, o[j][3] * inv1, ph, pl);
        *(uint32_t*)&g_att_hi[o1] = ph;
        *(uint32_t*)&g_att_lo[o1] = pl;
    }
}

// ---------------------------------------------------------------------------
// Launch
// ---------------------------------------------------------------------------
extern "C" void kernel_launch(void* const* d_in, const int* in_sizes, int n_in,
                              void* d_out, int out_size)
{
    const float* x      = (const float*)d_in[0];
    const float* W_qkv  = (const float*)d_in[1];
    const float* b_qkv  = (const float*)d_in[2];
    const float* W_out  = (const float*)d_in[3];
    const float* b_out  = (const float*)d_in[4];
    float* out = (float*)d_out;

    static bf16 *xh = nullptr, *xl, *wqh, *wql, *woh, *wol, *ath, *atl;
    static bool init_done = false;
    if (!init_done) {
        cudaGetSymbolAddress((void**)&xh,  g_x_hi);
        cudaGetSymbolAddress((void**)&xl,  g_x_lo);
        cudaGetSymbolAddress((void**)&wqh, g_wqkv_hi);
        cudaGetSymbolAddress((void**)&wql, g_wqkv_lo);
        cudaGetSymbolAddress((void**)&woh, g_wout_hi);
        cudaGetSymbolAddress((void**)&wol, g_wout_lo);
        cudaGetSymbolAddress((void**)&ath, g_att_hi);
        cudaGetSymbolAddress((void**)&atl, g_att_lo);
        cudaFuncSetAttribute(mma_gemm_kernel,
                             cudaFuncAttributeMaxDynamicSharedMemorySize,
                             G_SMEM_B);
        cudaFuncSetAttribute(attn_mma_kernel,
                             cudaFuncAttributeMaxDynamicSharedMemorySize,
                             ATT_SMEM_BYTES);
        init_done = true;
    }

    // 0) split conversions
    {
        int n4 = (TOKENS * D_MODEL) / 4;
        split_x_kernel<<<n4 / 256, 256>>>(x, xh, xl, n4);
        dim3 blk(32, 8);
        split_wt_kernel<<<dim3(QKV_COLS / 32, D_MODEL / 32), blk>>>(W_qkv, wqh, wql, QKV_COLS, D_MODEL);
        split_wt_kernel<<<dim3(D_MODEL / 32, D_MODEL / 32), blk>>>(W_out, woh, wol, D_MODEL, D_MODEL);
    }

    // 1) QKV projection -> split Q/K/Vt
    {
        dim3 grid(QKV_COLS / 128, TOKENS / 128);
        mma_gemm_kernel<<<grid, 256, G_SMEM_B>>>(xh, xl, wqh, wql, b_qkv, nullptr,
                                                 TOKENS, QKV_COLS, D_MODEL, 0);
    }

    // 2) Flash attention (mma.sync split-bf16, cp.async, 2 CTA/SM) -> split att
    {
        dim3 grid(N_SEQ / 128, BH);
        attn_mma_kernel<<<grid, 256, ATT_SMEM_BYTES>>>();
    }

    // 3) Output projection -> fp32 out
    {
        dim3 grid(D_MODEL / 128, TOKENS / 128);
        mma_gemm_kernel<<<grid, 256, G_SMEM_B>>>(ath, atl, woh, wol, b_out, out,
                                                 TOKENS, D_MODEL, D_MODEL, 1);
    }
}